// round 8
// baseline (speedup 1.0000x reference)
#include <cuda_runtime.h>
#include <cstdint>
#include <math.h>

// Sizes fixed: B=4, T=2048, E=1024, M=2048; R = B*T = 8192.
#define R_ROWS 8192
#define E_DIM  1024
#define M_DIM  2048
#define NCHUNK 16
#define TCH    128

// ---------------- scratch ----------------
__device__ float g_y [R_ROWS * E_DIM];
__device__ float g_b0[R_ROWS * M_DIM];
__device__ float g_b1[R_ROWS * M_DIM];   // yi (fp32) / zi (tf32-truncated)
__device__ float g_r [R_ROWS * M_DIM];
__device__ float g_og[R_ROWS * M_DIM];
__device__ float g_g [R_ROWS * M_DIM];
__device__ float g_x2[R_ROWS * E_DIM];
__device__ float g_z [R_ROWS * E_DIM];
__device__ float g_Ac[NCHUNK * 8192];
__device__ float g_Sc[NCHUNK * 8192];
__device__ float g_Hc[NCHUNK * 8192];
#define WSLOT (E_DIM * M_DIM)
__device__ float g_wT[8 * WSLOT];        // transposed + tf32-truncated weights [N][K]

__device__ __forceinline__ float sigm(float x) { return 1.f / (1.f + __expf(-x)); }

__device__ __forceinline__ uint32_t smem_u32(const void* p) {
    uint32_t a;
    asm("{ .reg .u64 t; cvta.to.shared.u64 t, %1; cvt.u32.u64 %0, t; }" : "=r"(a) : "l"(p));
    return a;
}

#define CP_ASYNC16(dst, src) asm volatile("cp.async.cg.shared.global [%0], [%1], 16;" :: "r"(dst), "l"(src))
#define CP_COMMIT()          asm volatile("cp.async.commit_group;" ::: "memory")
#define CP_WAIT1()           asm volatile("cp.async.wait_group 1;" ::: "memory")

__device__ __forceinline__ float f2tf32f(float v) {
    uint32_t r;
    asm("cvt.rna.tf32.f32 %0, %1;" : "=r"(r) : "f"(v));
    return __uint_as_float(r);
}

#define LDSM4(r0, r1, r2, r3, addr)                                            \
    asm volatile("ldmatrix.sync.aligned.m8n8.x4.shared.b16 {%0,%1,%2,%3}, [%4];" \
        : "=r"(r0), "=r"(r1), "=r"(r2), "=r"(r3) : "r"(addr))

#define MMA_TF32(c, a, b)                                                      \
    asm volatile("mma.sync.aligned.m16n8k8.row.col.f32.tf32.tf32.f32 "         \
        "{%0,%1,%2,%3}, {%4,%5,%6,%7}, {%8,%9}, {%0,%1,%2,%3};"                \
        : "+f"((c)[0]), "+f"((c)[1]), "+f"((c)[2]), "+f"((c)[3])               \
        : "r"((a)[0]), "r"((a)[1]), "r"((a)[2]), "r"((a)[3]),                  \
          "r"((b)[0]), "r"((b)[1]))

// ---------------- batched fused transpose + tf32 truncate ----------------
// For each weight w: src[K][N] -> dst[N][K], tf32-truncated.
struct TArgs { const float* s[8]; float* d[8]; int K[8]; int N[8]; };
__global__ __launch_bounds__(256) void tcvt8(TArgs a) {
    __shared__ float t[32][33];
    int w = blockIdx.y;
    int K = a.K[w], N = a.N[w];
    int nb = N >> 5;
    int bx = (blockIdx.x % nb) * 32;   // n
    int by = (blockIdx.x / nb) * 32;   // k
    const float* src = a.s[w];
    float* dst = a.d[w];
#pragma unroll
    for (int i = threadIdx.y; i < 32; i += 8)
        t[i][threadIdx.x] = src[(size_t)(by + i) * N + bx + threadIdx.x];
    __syncthreads();
#pragma unroll
    for (int i = threadIdx.y; i < 32; i += 8)
        dst[(size_t)(bx + i) * K + by + threadIdx.x] = f2tf32f(t[threadIdx.x][i]);
}

// ---------------- LayerNorm (rows of 1024), tf32-truncated output ----------------
__global__ __launch_bounds__(256) void ln1024(const float* __restrict__ x,
                                              const float* __restrict__ w,
                                              const float* __restrict__ b,
                                              float* __restrict__ y) {
    int row = blockIdx.x;
    const float4* xr = (const float4*)(x + (size_t)row * 1024);
    float4 v = xr[threadIdx.x];
    float s = v.x + v.y + v.z + v.w;
    float q = v.x * v.x + v.y * v.y + v.z * v.z + v.w * v.w;
#pragma unroll
    for (int o = 16; o; o >>= 1) {
        s += __shfl_xor_sync(0xFFFFFFFF, s, o);
        q += __shfl_xor_sync(0xFFFFFFFF, q, o);
    }
    __shared__ float ss[8], sq[8];
    int wid = threadIdx.x >> 5, lane = threadIdx.x & 31;
    if (lane == 0) { ss[wid] = s; sq[wid] = q; }
    __syncthreads();
    s = 0.f; q = 0.f;
#pragma unroll
    for (int i = 0; i < 8; i++) { s += ss[i]; q += sq[i]; }
    float mu  = s * (1.f / 1024.f);
    float var = q * (1.f / 1024.f) - mu * mu;
    float inv = rsqrtf(var + 1e-5f);
    float4 wv = ((const float4*)w)[threadIdx.x];
    float4 bv = ((const float4*)b)[threadIdx.x];
    float4 o;
    o.x = f2tf32f((v.x - mu) * inv * wv.x + bv.x);
    o.y = f2tf32f((v.y - mu) * inv * wv.y + bv.y);
    o.z = f2tf32f((v.z - mu) * inv * wv.z + bv.z);
    o.w = f2tf32f((v.w - mu) * inv * wv.w + bv.w);
    ((float4*)(y + (size_t)row * 1024))[threadIdx.x] = o;
}

// ---------------- tf32 mma GEMM: ldmatrix + BK=32, 3-stage cp.async ----------------
// C[m][n] = epi( sum_k A[m][k] * Bt[n][k] ),  A:[M,K] rm, Bt:[N,K] rm (both K-major).
// mode 0: raw  1: sigmoid(acc+bias)  2: resid*sigmoid(acc+bias)
//      3: acc(+bias)+resid  4: tf32(resid*sigmoid(acc+bias))
// CTA 128x128, BK=32, 3 stages. 256 thr = 8 warps (4m x 2n), warp tile 32x64.
#define NSTG  3
#define AST   36                    // 32 + 4 pad (words); 144B row stride -> conflict-free ldmatrix
#define AWRD  (128 * AST)           // 4608 words per tile (A or B)
#define STGW  (2 * AWRD)            // 9216 words / stage
#define GSMEM (NSTG * STGW * 4)     // 110592 bytes

__global__ __launch_bounds__(256, 2) void gemm_mma(const float* __restrict__ A,
                                                   const float* __restrict__ Bt,
                                                   const float* __restrict__ bias,
                                                   const float* __restrict__ resid,
                                                   float* __restrict__ C,
                                                   int K, int N, int mode) {
    extern __shared__ char smem[];
    uint32_t sbase = smem_u32(smem);

    int tid = threadIdx.x;
    int wid = tid >> 5, lane = tid & 31;
    int wm = wid & 3, wn = wid >> 2;
    int m0 = wm * 32, n0 = wn * 64;
    int grp = lane >> 2, ktid = lane & 3;
    int brow = blockIdx.y * 128, bcol = blockIdx.x * 128;

    // loads: each tile 128 rows x 32 k-words; thread -> row = tid>>1, cw = (tid&1)*16
    int lrow = tid >> 1, lcw = (tid & 1) * 16;
    const float* gA = A  + (size_t)(brow + lrow) * K + lcw;
    const float* gB = Bt + (size_t)(bcol + lrow) * K + lcw;
    uint32_t dA = sbase + (uint32_t)(lrow * AST + lcw) * 4;
    uint32_t dB = sbase + (uint32_t)(AWRD + lrow * AST + lcw) * 4;

    // ldmatrix per-lane addresses
    int l7 = lane & 7, lq = (lane >> 3) & 1, lh = lane >> 4;
    uint32_t aB = sbase + (uint32_t)(((m0 + lq * 8 + l7) * AST + lh * 4) * 4);
    uint32_t bB = sbase + (uint32_t)((AWRD + (n0 + lq * 8 + l7) * AST + lh * 4) * 4);

    float acc[2][8][4];
#pragma unroll
    for (int i = 0; i < 2; i++)
#pragma unroll
        for (int j = 0; j < 8; j++)
#pragma unroll
            for (int v = 0; v < 4; v++) acc[i][j][v] = 0.f;

    const int nk = K / 32;

    // prologue: fill 2 stages
#pragma unroll
    for (int p = 0; p < NSTG - 1; p++) {
        uint32_t o = (uint32_t)p * (STGW * 4);
        const float* a = gA + p * 32;
        const float* b = gB + p * 32;
#pragma unroll
        for (int u = 0; u < 4; u++) {
            CP_ASYNC16(dA + o + u * 16, a + u * 4);
            CP_ASYNC16(dB + o + u * 16, b + u * 4);
        }
        CP_COMMIT();
    }

    int slot = 0;
    for (int kt = 0; kt < nk; kt++) {
        CP_WAIT1();
        __syncthreads();

        if (kt + NSTG - 1 < nk) {
            int ws = slot + (NSTG - 1);
            if (ws >= NSTG) ws -= NSTG;
            uint32_t o = (uint32_t)ws * (STGW * 4);
            const float* a = gA + (kt + NSTG - 1) * 32;
            const float* b = gB + (kt + NSTG - 1) * 32;
#pragma unroll
            for (int u = 0; u < 4; u++) {
                CP_ASYNC16(dA + o + u * 16, a + u * 4);
                CP_ASYNC16(dB + o + u * 16, b + u * 4);
            }
        }
        CP_COMMIT();

        uint32_t so = (uint32_t)slot * (STGW * 4);

#pragma unroll
        for (int ks = 0; ks < 4; ks++) {
            uint32_t af[2][4], bf[8][2];
#pragma unroll
            for (int mi = 0; mi < 2; mi++)
                LDSM4(af[mi][0], af[mi][1], af[mi][2], af[mi][3],
                      aB + so + (uint32_t)(mi * 16 * AST * 4) + (uint32_t)(ks * 32));
#pragma unroll
            for (int p = 0; p < 4; p++)
                LDSM4(bf[2 * p][0], bf[2 * p + 1][0], bf[2 * p][1], bf[2 * p + 1][1],
                      bB + so + (uint32_t)(p * 16 * AST * 4) + (uint32_t)(ks * 32));
#pragma unroll
            for (int mi = 0; mi < 2; mi++)
#pragma unroll
                for (int ni = 0; ni < 8; ni++)
                    MMA_TF32(acc[mi][ni], af[mi], bf[ni]);
        }

        if (++slot == NSTG) slot = 0;
    }

    // ---------------- epilogue ----------------
#pragma unroll
    for (int mi = 0; mi < 2; mi++) {
#pragma unroll
        for (int ni = 0; ni < 8; ni++) {
            int row = brow + m0 + mi * 16 + grp;
            int col = bcol + n0 + ni * 8 + ktid * 2;
            float b0v = 0.f, b1v = 0.f;
            if ((mode != 0) && bias) { b0v = bias[col]; b1v = bias[col + 1]; }
#pragma unroll
            for (int half = 0; half < 2; half++) {
                int r = row + half * 8;
                float v0 = acc[mi][ni][half * 2 + 0] + b0v;
                float v1 = acc[mi][ni][half * 2 + 1] + b1v;
                if (mode == 1 || mode == 2 || mode == 4) { v0 = sigm(v0); v1 = sigm(v1); }
                size_t off = (size_t)r * N + col;
                if (mode == 2 || mode == 4) {
                    float2 rr = *(const float2*)(resid + off);
                    v0 *= rr.x; v1 *= rr.y;
                    if (mode == 4) { v0 = f2tf32f(v0); v1 = f2tf32f(v1); }
                } else if (mode == 3) {
                    float2 rr = *(const float2*)(resid + off);
                    v0 += rr.x; v1 += rr.y;
                }
                float2 o; o.x = v0; o.y = v1;
                *(float2*)(C + off) = o;
            }
        }
    }
}

// ---------------- chunked scan: h_t = r_t*h_{t-1} + yi_t ----------------
__global__ __launch_bounds__(256) void scan_pass1(const float* __restrict__ yi,
                                                  const float* __restrict__ rb,
                                                  float* __restrict__ Ac,
                                                  float* __restrict__ Sc) {
    int idx = blockIdx.x * 256 + threadIdx.x;
    int ch  = idx & 8191;
    int c   = idx >> 13;
    int b   = ch >> 11;
    int base = (b * 2048 + c * TCH) * 2048 + (ch & 2047);
    float A = 1.f, S = 0.f;
#pragma unroll 4
    for (int t = 0; t < TCH; t++) {
        float rr = rb[base];
        S = fmaf(rr, S, yi[base]);
        A *= rr;
        base += 2048;
    }
    Ac[idx] = A;
    Sc[idx] = S;
}

__global__ __launch_bounds__(256) void scan_pass2(const float* __restrict__ mem,
                                                  const float* __restrict__ Ac,
                                                  const float* __restrict__ Sc,
                                                  float* __restrict__ Hc,
                                                  float* __restrict__ memout) {
    int ch = blockIdx.x * 256 + threadIdx.x;
    float h = mem[ch];
#pragma unroll
    for (int c = 0; c < NCHUNK; c++) {
        int i = c * 8192 + ch;
        Hc[i] = h;
        h = fmaf(Ac[i], h, Sc[i]);
    }
    memout[ch] = h;
}

__global__ __launch_bounds__(256) void scan_pass3(const float* __restrict__ yi,
                                                  const float* __restrict__ rb,
                                                  const float* __restrict__ og,
                                                  const float* __restrict__ Hc,
                                                  float* __restrict__ g) {
    int idx = blockIdx.x * 256 + threadIdx.x;
    int ch  = idx & 8191;
    int c   = idx >> 13;
    int b   = ch >> 11;
    int base = (b * 2048 + c * TCH) * 2048 + (ch & 2047);
    float h = Hc[idx];
#pragma unroll 4
    for (int t = 0; t < TCH; t++) {
        float rr = rb[base];
        h = fmaf(rr, h, yi[base]);
        float s = h / (1.f + fabsf(h));
        g[base] = f2tf32f(s * og[base]);   // tf32: g is GEMM-A-only
        base += 2048;
    }
}

// ---------------- host launch ----------------
extern "C" void kernel_launch(void* const* d_in, const int* in_sizes, int n_in,
                              void* d_out, int out_size) {
    const float* x    = (const float*)d_in[0];
    const float* mem  = (const float*)d_in[1];
    const float* ln1w = (const float*)d_in[2];
    const float* ln1b = (const float*)d_in[3];
    const float* wf   = (const float*)d_in[4];
    const float* wfb  = (const float*)d_in[5];
    const float* wi   = (const float*)d_in[6];
    const float* wig  = (const float*)d_in[7];
    const float* wigb = (const float*)d_in[8];
    const float* wog  = (const float*)d_in[9];
    const float* wogb = (const float*)d_in[10];
    const float* wo   = (const float*)d_in[11];
    const float* ln2w = (const float*)d_in[12];
    const float* ln2b = (const float*)d_in[13];
    const float* fwi  = (const float*)d_in[14];
    const float* fwg  = (const float*)d_in[15];
    const float* fwgb = (const float*)d_in[16];
    const float* fwo  = (const float*)d_in[17];
    const float* fwob = (const float*)d_in[18];
    float* out = (float*)d_out;

    float *y, *b0, *b1, *rb, *og, *g, *x2, *z, *Ac, *Sc, *Hc, *wT;
    cudaGetSymbolAddress((void**)&y,  g_y);
    cudaGetSymbolAddress((void**)&b0, g_b0);
    cudaGetSymbolAddress((void**)&b1, g_b1);
    cudaGetSymbolAddress((void**)&rb, g_r);
    cudaGetSymbolAddress((void**)&og, g_og);
    cudaGetSymbolAddress((void**)&g,  g_g);
    cudaGetSymbolAddress((void**)&x2, g_x2);
    cudaGetSymbolAddress((void**)&z,  g_z);
    cudaGetSymbolAddress((void**)&Ac, g_Ac);
    cudaGetSymbolAddress((void**)&Sc, g_Sc);
    cudaGetSymbolAddress((void**)&Hc, g_Hc);
    cudaGetSymbolAddress((void**)&wT, g_wT);

    cudaFuncSetAttribute(gemm_mma, cudaFuncAttributeMaxDynamicSharedMemorySize, GSMEM);

    float* wiT  = wT + 0 * WSLOT;
    float* wigT = wT + 1 * WSLOT;
    float* wfT  = wT + 2 * WSLOT;
    float* wogT = wT + 3 * WSLOT;
    float* woT  = wT + 4 * WSLOT;
    float* fwiT = wT + 5 * WSLOT;
    float* fwgT = wT + 6 * WSLOT;
    float* fwoT = wT + 7 * WSLOT;

    TArgs ta;
    ta.s[0] = wi;  ta.d[0] = wiT;  ta.K[0] = E_DIM; ta.N[0] = M_DIM;
    ta.s[1] = wig; ta.d[1] = wigT; ta.K[1] = E_DIM; ta.N[1] = M_DIM;
    ta.s[2] = wf;  ta.d[2] = wfT;  ta.K[2] = E_DIM; ta.N[2] = M_DIM;
    ta.s[3] = wog; ta.d[3] = wogT; ta.K[3] = E_DIM; ta.N[3] = M_DIM;
    ta.s[4] = wo;  ta.d[4] = woT;  ta.K[4] = M_DIM; ta.N[4] = E_DIM;
    ta.s[5] = fwi; ta.d[5] = fwiT; ta.K[5] = E_DIM; ta.N[5] = M_DIM;
    ta.s[6] = fwg; ta.d[6] = fwgT; ta.K[6] = E_DIM; ta.N[6] = M_DIM;
    ta.s[7] = fwo; ta.d[7] = fwoT; ta.K[7] = M_DIM; ta.N[7] = E_DIM;
    dim3 tg(WSLOT / (32 * 32), 8);   // 2048 x 8
    tcvt8<<<tg, dim3(32, 8)>>>(ta);

    ln1024<<<R_ROWS, 256>>>(x, ln1w, ln1b, y);

    dim3 gM(M_DIM / 128, R_ROWS / 128);
    dim3 gE(E_DIM / 128, R_ROWS / 128);

    gemm_mma<<<gM, 256, GSMEM>>>(y, wiT,  nullptr, nullptr, b0, E_DIM, M_DIM, 0);
    gemm_mma<<<gM, 256, GSMEM>>>(y, wigT, wigb,    b0,      b1, E_DIM, M_DIM, 2); // yi fp32
    gemm_mma<<<gM, 256, GSMEM>>>(y, wfT,  wfb,     nullptr, rb, E_DIM, M_DIM, 1);
    gemm_mma<<<gM, 256, GSMEM>>>(y, wogT, wogb,    nullptr, og, E_DIM, M_DIM, 1);

    scan_pass1<<<NCHUNK * 8192 / 256, 256>>>(b1, rb, Ac, Sc);
    scan_pass2<<<8192 / 256, 256>>>(mem, Ac, Sc, Hc, out + (size_t)R_ROWS * E_DIM);
    scan_pass3<<<NCHUNK * 8192 / 256, 256>>>(b1, rb, og, Hc, g);

    gemm_mma<<<gE, 256, GSMEM>>>(g, woT, nullptr, x, x2, M_DIM, E_DIM, 3);

    ln1024<<<R_ROWS, 256>>>(x2, ln2w, ln2b, z);

    gemm_mma<<<gM, 256, GSMEM>>>(z,  fwiT, nullptr, nullptr, b0,  E_DIM, M_DIM, 0);
    gemm_mma<<<gM, 256, GSMEM>>>(z,  fwgT, fwgb,    b0,      b1,  E_DIM, M_DIM, 4); // zi tf32
    gemm_mma<<<gE, 256, GSMEM>>>(b1, fwoT, fwob,    x2,      out, M_DIM, E_DIM, 3);
}

// round 9
// speedup vs baseline: 1.1505x; 1.1505x over previous
#include <cuda_runtime.h>
#include <cstdint>
#include <math.h>

// Sizes fixed: B=4, T=2048, E=1024, M=2048; R = B*T = 8192.
#define R_ROWS 8192
#define E_DIM  1024
#define M_DIM  2048
#define NCHUNK 16
#define TCH    128

// ---------------- scratch ----------------
__device__ float g_y [R_ROWS * E_DIM];
__device__ float g_b0[R_ROWS * M_DIM];
__device__ float g_b1[R_ROWS * M_DIM];
__device__ float g_r [R_ROWS * M_DIM];
__device__ float g_og[R_ROWS * M_DIM];
__device__ float g_g [R_ROWS * M_DIM];   // gate output, later zi
__device__ float g_x2[R_ROWS * E_DIM];
__device__ float g_z [R_ROWS * E_DIM];
__device__ float g_Ac[NCHUNK * 8192];
__device__ float g_Sc[NCHUNK * 8192];
__device__ float g_Hc[NCHUNK * 8192];
#define WSLOT (E_DIM * M_DIM)
__device__ float g_wT[8 * WSLOT];        // transposed + tf32-truncated weights [N][K]

__device__ __forceinline__ float sigm(float x) { return 1.f / (1.f + __expf(-x)); }

__device__ __forceinline__ uint32_t smem_u32(const void* p) {
    uint32_t a;
    asm("{ .reg .u64 t; cvta.to.shared.u64 t, %1; cvt.u32.u64 %0, t; }" : "=r"(a) : "l"(p));
    return a;
}

#define CP_ASYNC16(dst, src) asm volatile("cp.async.cg.shared.global [%0], [%1], 16;" :: "r"(dst), "l"(src))
#define CP_COMMIT()          asm volatile("cp.async.commit_group;" ::: "memory")
#define CP_WAIT2()           asm volatile("cp.async.wait_group 2;" ::: "memory")

__device__ __forceinline__ float f2tf32f(float v) {
    uint32_t r;
    asm("cvt.rna.tf32.f32 %0, %1;" : "=r"(r) : "f"(v));
    return __uint_as_float(r);
}

#define LDSM4(r0, r1, r2, r3, addr)                                            \
    asm volatile("ldmatrix.sync.aligned.m8n8.x4.shared.b16 {%0,%1,%2,%3}, [%4];" \
        : "=r"(r0), "=r"(r1), "=r"(r2), "=r"(r3) : "r"(addr))

#define MMA_TF32(c, a, b)                                                      \
    asm volatile("mma.sync.aligned.m16n8k8.row.col.f32.tf32.tf32.f32 "         \
        "{%0,%1,%2,%3}, {%4,%5,%6,%7}, {%8,%9}, {%0,%1,%2,%3};"                \
        : "+f"((c)[0]), "+f"((c)[1]), "+f"((c)[2]), "+f"((c)[3])               \
        : "r"((a)[0]), "r"((a)[1]), "r"((a)[2]), "r"((a)[3]),                  \
          "r"((b)[0]), "r"((b)[1]))

// ---------------- batched fused transpose + tf32 truncate ----------------
struct TArgs { const float* s[8]; float* d[8]; int K[8]; int N[8]; };
__global__ __launch_bounds__(256) void tcvt8(TArgs a) {
    __shared__ float t[32][33];
    int w = blockIdx.y;
    int K = a.K[w], N = a.N[w];
    int nb = N >> 5;
    int bx = (blockIdx.x % nb) * 32;
    int by = (blockIdx.x / nb) * 32;
    const float* src = a.s[w];
    float* dst = a.d[w];
#pragma unroll
    for (int i = threadIdx.y; i < 32; i += 8)
        t[i][threadIdx.x] = src[(size_t)(by + i) * N + bx + threadIdx.x];
    __syncthreads();
#pragma unroll
    for (int i = threadIdx.y; i < 32; i += 8)
        dst[(size_t)(bx + i) * K + by + threadIdx.x] = f2tf32f(t[threadIdx.x][i]);
}

// ---------------- LayerNorm (rows of 1024), tf32-truncated output ----------------
__global__ __launch_bounds__(256) void ln1024(const float* __restrict__ x,
                                              const float* __restrict__ w,
                                              const float* __restrict__ b,
                                              float* __restrict__ y) {
    int row = blockIdx.x;
    const float4* xr = (const float4*)(x + (size_t)row * 1024);
    float4 v = xr[threadIdx.x];
    float s = v.x + v.y + v.z + v.w;
    float q = v.x * v.x + v.y * v.y + v.z * v.z + v.w * v.w;
#pragma unroll
    for (int o = 16; o; o >>= 1) {
        s += __shfl_xor_sync(0xFFFFFFFF, s, o);
        q += __shfl_xor_sync(0xFFFFFFFF, q, o);
    }
    __shared__ float ss[8], sq[8];
    int wid = threadIdx.x >> 5, lane = threadIdx.x & 31;
    if (lane == 0) { ss[wid] = s; sq[wid] = q; }
    __syncthreads();
    s = 0.f; q = 0.f;
#pragma unroll
    for (int i = 0; i < 8; i++) { s += ss[i]; q += sq[i]; }
    float mu  = s * (1.f / 1024.f);
    float var = q * (1.f / 1024.f) - mu * mu;
    float inv = rsqrtf(var + 1e-5f);
    float4 wv = ((const float4*)w)[threadIdx.x];
    float4 bv = ((const float4*)b)[threadIdx.x];
    float4 o;
    o.x = f2tf32f((v.x - mu) * inv * wv.x + bv.x);
    o.y = f2tf32f((v.y - mu) * inv * wv.y + bv.y);
    o.z = f2tf32f((v.z - mu) * inv * wv.z + bv.z);
    o.w = f2tf32f((v.w - mu) * inv * wv.w + bv.w);
    ((float4*)(y + (size_t)row * 1024))[threadIdx.x] = o;
}

// ---------------- tf32 mma GEMM, batched over blockIdx.z ----------------
// Per z: C[m][n] = epi( sum_k A[m][k] * Bt[n][k] ). A shared across z.
// mode 0: raw   1: sigmoid(acc+bias)   3: acc(+bias)+resid
// CTA 128x128, BK=16, 4 stages. 256 thr = 8 warps (4m x 2n), warp tile 32x64.
#define NSTG  4
#define AST   20
#define AWRD  (128 * AST)
#define STGW  (2 * AWRD)
#define GSMEM (NSTG * STGW * 4)     // 81920 bytes

struct GB { const float* Bt; const float* bias; const float* resid; float* C; int mode; };
struct GArgs { GB g[4]; };

__global__ __launch_bounds__(256, 2) void gemm_mma(const float* __restrict__ A,
                                                   GArgs ga, int K, int N) {
    extern __shared__ char smem[];
    uint32_t sbase = smem_u32(smem);

    GB gb = ga.g[blockIdx.z];
    const float* __restrict__ Bt = gb.Bt;

    int tid = threadIdx.x;
    int wid = tid >> 5, lane = tid & 31;
    int wm = wid & 3, wn = wid >> 2;
    int m0 = wm * 32, n0 = wn * 64;
    int grp = lane >> 2, ktid = lane & 3;
    int brow = blockIdx.y * 128, bcol = blockIdx.x * 128;

    int lrow = tid >> 1, lcw = (tid & 1) * 8;
    const float* gA = A  + (size_t)(brow + lrow) * K + lcw;
    const float* gB = Bt + (size_t)(bcol + lrow) * K + lcw;
    uint32_t dA = sbase + (uint32_t)(lrow * AST + lcw) * 4;
    uint32_t dB = sbase + (uint32_t)(AWRD + lrow * AST + lcw) * 4;

    int l7 = lane & 7, lq = (lane >> 3) & 1, lh = lane >> 4;
    uint32_t aB = sbase + (uint32_t)(((m0 + lq * 8 + l7) * AST + lh * 4) * 4);
    uint32_t bB = sbase + (uint32_t)((AWRD + (n0 + lq * 8 + l7) * AST + lh * 4) * 4);

    float acc[2][8][4];
#pragma unroll
    for (int i = 0; i < 2; i++)
#pragma unroll
        for (int j = 0; j < 8; j++)
#pragma unroll
            for (int v = 0; v < 4; v++) acc[i][j][v] = 0.f;

    const int nk = K / 16;

#pragma unroll
    for (int p = 0; p < NSTG - 1; p++) {
        uint32_t o = (uint32_t)p * (STGW * 4);
        const float* a = gA + p * 16;
        const float* b = gB + p * 16;
        CP_ASYNC16(dA + o, a);      CP_ASYNC16(dA + o + 16, a + 4);
        CP_ASYNC16(dB + o, b);      CP_ASYNC16(dB + o + 16, b + 4);
        CP_COMMIT();
    }

    for (int kt = 0; kt < nk; kt++) {
        CP_WAIT2();
        __syncthreads();

        if (kt + NSTG - 1 < nk) {
            uint32_t o = (uint32_t)((kt + NSTG - 1) & (NSTG - 1)) * (STGW * 4);
            const float* a = gA + (kt + NSTG - 1) * 16;
            const float* b = gB + (kt + NSTG - 1) * 16;
            CP_ASYNC16(dA + o, a);      CP_ASYNC16(dA + o + 16, a + 4);
            CP_ASYNC16(dB + o, b);      CP_ASYNC16(dB + o + 16, b + 4);
        }
        CP_COMMIT();

        uint32_t so = (uint32_t)(kt & (NSTG - 1)) * (STGW * 4);

#pragma unroll
        for (int ks = 0; ks < 2; ks++) {
            uint32_t af[2][4], bf[8][2];
#pragma unroll
            for (int mi = 0; mi < 2; mi++)
                LDSM4(af[mi][0], af[mi][1], af[mi][2], af[mi][3],
                      aB + so + (uint32_t)(mi * 16 * AST * 4) + (uint32_t)(ks * 32));
#pragma unroll
            for (int p = 0; p < 4; p++)
                LDSM4(bf[2 * p][0], bf[2 * p + 1][0], bf[2 * p][1], bf[2 * p + 1][1],
                      bB + so + (uint32_t)(p * 16 * AST * 4) + (uint32_t)(ks * 32));
#pragma unroll
            for (int mi = 0; mi < 2; mi++)
#pragma unroll
                for (int ni = 0; ni < 8; ni++)
                    MMA_TF32(acc[mi][ni], af[mi], bf[ni]);
        }
    }

    // ---------------- epilogue ----------------
    int mode = gb.mode;
    const float* bias = gb.bias;
    const float* resid = gb.resid;
    float* C = gb.C;
#pragma unroll
    for (int mi = 0; mi < 2; mi++) {
#pragma unroll
        for (int ni = 0; ni < 8; ni++) {
            int row = brow + m0 + mi * 16 + grp;
            int col = bcol + n0 + ni * 8 + ktid * 2;
            float b0v = 0.f, b1v = 0.f;
            if ((mode != 0) && bias) { b0v = bias[col]; b1v = bias[col + 1]; }
#pragma unroll
            for (int half = 0; half < 2; half++) {
                int r = row + half * 8;
                float v0 = acc[mi][ni][half * 2 + 0] + b0v;
                float v1 = acc[mi][ni][half * 2 + 1] + b1v;
                if (mode == 1) { v0 = sigm(v0); v1 = sigm(v1); }
                size_t off = (size_t)r * N + col;
                if (mode == 3) {
                    float2 rr = *(const float2*)(resid + off);
                    v0 += rr.x; v1 += rr.y;
                }
                float2 o; o.x = v0; o.y = v1;
                *(float2*)(C + off) = o;
            }
        }
    }
}

// ---------------- zi = tf32(b0 * b1) elementwise ----------------
__global__ __launch_bounds__(256) void gateprod(const float* __restrict__ b0,
                                                const float* __restrict__ b1,
                                                float* __restrict__ o) {
    int i = blockIdx.x * 256 + threadIdx.x;
    float4 a = ((const float4*)b0)[i];
    float4 b = ((const float4*)b1)[i];
    a.x = f2tf32f(a.x * b.x);
    a.y = f2tf32f(a.y * b.y);
    a.z = f2tf32f(a.z * b.z);
    a.w = f2tf32f(a.w * b.w);
    ((float4*)o)[i] = a;
}

// ---------------- chunked scan: h_t = r_t*h_{t-1} + yi_t,  yi = b0*b1 ----------------
__global__ __launch_bounds__(256) void scan_pass1(const float* __restrict__ b0,
                                                  const float* __restrict__ b1,
                                                  const float* __restrict__ rb,
                                                  float* __restrict__ Ac,
                                                  float* __restrict__ Sc) {
    int idx = blockIdx.x * 256 + threadIdx.x;
    int ch  = idx & 8191;
    int c   = idx >> 13;
    int b   = ch >> 11;
    int base = (b * 2048 + c * TCH) * 2048 + (ch & 2047);
    float A = 1.f, S = 0.f;
#pragma unroll 4
    for (int t = 0; t < TCH; t++) {
        float rr = rb[base];
        S = fmaf(rr, S, b0[base] * b1[base]);
        A *= rr;
        base += 2048;
    }
    Ac[idx] = A;
    Sc[idx] = S;
}

__global__ __launch_bounds__(256) void scan_pass2(const float* __restrict__ mem,
                                                  const float* __restrict__ Ac,
                                                  const float* __restrict__ Sc,
                                                  float* __restrict__ Hc,
                                                  float* __restrict__ memout) {
    int ch = blockIdx.x * 256 + threadIdx.x;
    float h = mem[ch];
#pragma unroll
    for (int c = 0; c < NCHUNK; c++) {
        int i = c * 8192 + ch;
        Hc[i] = h;
        h = fmaf(Ac[i], h, Sc[i]);
    }
    memout[ch] = h;
}

__global__ __launch_bounds__(256) void scan_pass3(const float* __restrict__ b0,
                                                  const float* __restrict__ b1,
                                                  const float* __restrict__ rb,
                                                  const float* __restrict__ og,
                                                  const float* __restrict__ Hc,
                                                  float* __restrict__ g) {
    int idx = blockIdx.x * 256 + threadIdx.x;
    int ch  = idx & 8191;
    int c   = idx >> 13;
    int b   = ch >> 11;
    int base = (b * 2048 + c * TCH) * 2048 + (ch & 2047);
    float h = Hc[idx];
#pragma unroll 4
    for (int t = 0; t < TCH; t++) {
        float rr = rb[base];
        h = fmaf(rr, h, b0[base] * b1[base]);
        float s = h / (1.f + fabsf(h));
        g[base] = f2tf32f(s * og[base]);
        base += 2048;
    }
}

// ---------------- host launch ----------------
extern "C" void kernel_launch(void* const* d_in, const int* in_sizes, int n_in,
                              void* d_out, int out_size) {
    const float* x    = (const float*)d_in[0];
    const float* mem  = (const float*)d_in[1];
    const float* ln1w = (const float*)d_in[2];
    const float* ln1b = (const float*)d_in[3];
    const float* wf   = (const float*)d_in[4];
    const float* wfb  = (const float*)d_in[5];
    const float* wi   = (const float*)d_in[6];
    const float* wig  = (const float*)d_in[7];
    const float* wigb = (const float*)d_in[8];
    const float* wog  = (const float*)d_in[9];
    const float* wogb = (const float*)d_in[10];
    const float* wo   = (const float*)d_in[11];
    const float* ln2w = (const float*)d_in[12];
    const float* ln2b = (const float*)d_in[13];
    const float* fwi  = (const float*)d_in[14];
    const float* fwg  = (const float*)d_in[15];
    const float* fwgb = (const float*)d_in[16];
    const float* fwo  = (const float*)d_in[17];
    const float* fwob = (const float*)d_in[18];
    float* out = (float*)d_out;

    float *y, *b0, *b1, *rb, *og, *g, *x2, *z, *Ac, *Sc, *Hc, *wT;
    cudaGetSymbolAddress((void**)&y,  g_y);
    cudaGetSymbolAddress((void**)&b0, g_b0);
    cudaGetSymbolAddress((void**)&b1, g_b1);
    cudaGetSymbolAddress((void**)&rb, g_r);
    cudaGetSymbolAddress((void**)&og, g_og);
    cudaGetSymbolAddress((void**)&g,  g_g);
    cudaGetSymbolAddress((void**)&x2, g_x2);
    cudaGetSymbolAddress((void**)&z,  g_z);
    cudaGetSymbolAddress((void**)&Ac, g_Ac);
    cudaGetSymbolAddress((void**)&Sc, g_Sc);
    cudaGetSymbolAddress((void**)&Hc, g_Hc);
    cudaGetSymbolAddress((void**)&wT, g_wT);

    cudaFuncSetAttribute(gemm_mma, cudaFuncAttributeMaxDynamicSharedMemorySize, GSMEM);

    float* wiT  = wT + 0 * WSLOT;
    float* wigT = wT + 1 * WSLOT;
    float* wfT  = wT + 2 * WSLOT;
    float* wogT = wT + 3 * WSLOT;
    float* woT  = wT + 4 * WSLOT;
    float* fwiT = wT + 5 * WSLOT;
    float* fwgT = wT + 6 * WSLOT;
    float* fwoT = wT + 7 * WSLOT;

    TArgs ta;
    ta.s[0] = wi;  ta.d[0] = wiT;  ta.K[0] = E_DIM; ta.N[0] = M_DIM;
    ta.s[1] = wig; ta.d[1] = wigT; ta.K[1] = E_DIM; ta.N[1] = M_DIM;
    ta.s[2] = wf;  ta.d[2] = wfT;  ta.K[2] = E_DIM; ta.N[2] = M_DIM;
    ta.s[3] = wog; ta.d[3] = wogT; ta.K[3] = E_DIM; ta.N[3] = M_DIM;
    ta.s[4] = wo;  ta.d[4] = woT;  ta.K[4] = M_DIM; ta.N[4] = E_DIM;
    ta.s[5] = fwi; ta.d[5] = fwiT; ta.K[5] = E_DIM; ta.N[5] = M_DIM;
    ta.s[6] = fwg; ta.d[6] = fwgT; ta.K[6] = E_DIM; ta.N[6] = M_DIM;
    ta.s[7] = fwo; ta.d[7] = fwoT; ta.K[7] = M_DIM; ta.N[7] = E_DIM;
    dim3 tg(WSLOT / (32 * 32), 8);
    tcvt8<<<tg, dim3(32, 8)>>>(ta);

    ln1024<<<R_ROWS, 256>>>(x, ln1w, ln1b, y);

    // 4 gate GEMMs in one launch (independent; yi formed in scan)
    {
        GArgs ga;
        ga.g[0] = { wiT,  nullptr, nullptr, b0, 0 };
        ga.g[1] = { wigT, wigb,    nullptr, b1, 1 };
        ga.g[2] = { wfT,  wfb,     nullptr, rb, 1 };
        ga.g[3] = { wogT, wogb,    nullptr, og, 1 };
        dim3 gr(M_DIM / 128, R_ROWS / 128, 4);
        gemm_mma<<<gr, 256, GSMEM>>>(y, ga, E_DIM, M_DIM);
    }

    scan_pass1<<<NCHUNK * 8192 / 256, 256>>>(b0, b1, rb, Ac, Sc);
    scan_pass2<<<8192 / 256, 256>>>(mem, Ac, Sc, Hc, out + (size_t)R_ROWS * E_DIM);
    scan_pass3<<<NCHUNK * 8192 / 256, 256>>>(b0, b1, rb, og, Hc, g);

    // x2 = x + g @ wo
    {
        GArgs ga;
        ga.g[0] = { woT, nullptr, x, x2, 3 };
        dim3 gr(E_DIM / 128, R_ROWS / 128, 1);
        gemm_mma<<<gr, 256, GSMEM>>>(g, ga, M_DIM, E_DIM);
    }

    ln1024<<<R_ROWS, 256>>>(x2, ln2w, ln2b, z);

    // FFN in+gate in one launch
    {
        GArgs ga;
        ga.g[0] = { fwiT, nullptr, nullptr, b0, 0 };
        ga.g[1] = { fwgT, fwgb,    nullptr, b1, 1 };
        dim3 gr(M_DIM / 128, R_ROWS / 128, 2);
        gemm_mma<<<gr, 256, GSMEM>>>(z, ga, E_DIM, M_DIM);
    }

    // zi = tf32(b0*b1) into g
    gateprod<<<R_ROWS * M_DIM / 4 / 256, 256>>>(b0, b1, g);

    // out = x2 + zi @ fwo + fwob
    {
        GArgs ga;
        ga.g[0] = { fwoT, fwob, x2, out, 3 };
        dim3 gr(E_DIM / 128, R_ROWS / 128, 1);
        gemm_mma<<<gr, 256, GSMEM>>>(g, ga, M_DIM, E_DIM);
    }
}

// round 10
// speedup vs baseline: 1.1744x; 1.0208x over previous
#include <cuda_runtime.h>
#include <cstdint>
#include <math.h>

// Sizes fixed: B=4, T=2048, E=1024, M=2048; R = B*T = 8192.
#define R_ROWS 8192
#define E_DIM  1024
#define M_DIM  2048
#define NCHUNK 16
#define TCH    128

// ---------------- scratch ----------------
__device__ float g_y [R_ROWS * E_DIM];
__device__ float g_b0[R_ROWS * M_DIM];
__device__ float g_b1[R_ROWS * M_DIM];
__device__ float g_r [R_ROWS * M_DIM];
__device__ float g_og[R_ROWS * M_DIM];
__device__ float g_g [R_ROWS * M_DIM];   // gate output, later zi
__device__ float g_x2[R_ROWS * E_DIM];
__device__ float g_z [R_ROWS * E_DIM];
__device__ float g_Ac[NCHUNK * 8192];
__device__ float g_Sc[NCHUNK * 8192];
__device__ float g_Hc[NCHUNK * 8192];
#define WSLOT (E_DIM * M_DIM)
__device__ float g_wT[8 * WSLOT];        // transposed + tf32-truncated weights [N][K]

__device__ __forceinline__ float sigm(float x) { return 1.f / (1.f + __expf(-x)); }

__device__ __forceinline__ uint32_t smem_u32(const void* p) {
    uint32_t a;
    asm("{ .reg .u64 t; cvta.to.shared.u64 t, %1; cvt.u32.u64 %0, t; }" : "=r"(a) : "l"(p));
    return a;
}

#define CP_ASYNC16(dst, src) asm volatile("cp.async.cg.shared.global [%0], [%1], 16;" :: "r"(dst), "l"(src))
#define CP_COMMIT()          asm volatile("cp.async.commit_group;" ::: "memory")
#define CP_WAIT2()           asm volatile("cp.async.wait_group 2;" ::: "memory")

__device__ __forceinline__ float f2tf32f(float v) {
    uint32_t r;
    asm("cvt.rna.tf32.f32 %0, %1;" : "=r"(r) : "f"(v));
    return __uint_as_float(r);
}

#define LDSM4(r0, r1, r2, r3, addr)                                            \
    asm volatile("ldmatrix.sync.aligned.m8n8.x4.shared.b16 {%0,%1,%2,%3}, [%4];" \
        : "=r"(r0), "=r"(r1), "=r"(r2), "=r"(r3) : "r"(addr))

#define MMA_TF32(c, a, b)                                                      \
    asm volatile("mma.sync.aligned.m16n8k8.row.col.f32.tf32.tf32.f32 "         \
        "{%0,%1,%2,%3}, {%4,%5,%6,%7}, {%8,%9}, {%0,%1,%2,%3};"                \
        : "+f"((c)[0]), "+f"((c)[1]), "+f"((c)[2]), "+f"((c)[3])               \
        : "r"((a)[0]), "r"((a)[1]), "r"((a)[2]), "r"((a)[3]),                  \
          "r"((b)[0]), "r"((b)[1]))

// ---------------- batched fused transpose + tf32 truncate ----------------
struct TArgs { const float* s[8]; float* d[8]; int K[8]; int N[8]; };
__global__ __launch_bounds__(256) void tcvt8(TArgs a) {
    __shared__ float t[32][33];
    int w = blockIdx.y;
    int K = a.K[w], N = a.N[w];
    int nb = N >> 5;
    int bx = (blockIdx.x % nb) * 32;
    int by = (blockIdx.x / nb) * 32;
    const float* src = a.s[w];
    float* dst = a.d[w];
#pragma unroll
    for (int i = threadIdx.y; i < 32; i += 8)
        t[i][threadIdx.x] = src[(size_t)(by + i) * N + bx + threadIdx.x];
    __syncthreads();
#pragma unroll
    for (int i = threadIdx.y; i < 32; i += 8)
        dst[(size_t)(bx + i) * K + by + threadIdx.x] = f2tf32f(t[threadIdx.x][i]);
}

// ---------------- LayerNorm (rows of 1024), tf32-truncated output ----------------
__global__ __launch_bounds__(256) void ln1024(const float* __restrict__ x,
                                              const float* __restrict__ w,
                                              const float* __restrict__ b,
                                              float* __restrict__ y) {
    int row = blockIdx.x;
    const float4* xr = (const float4*)(x + (size_t)row * 1024);
    float4 v = xr[threadIdx.x];
    float s = v.x + v.y + v.z + v.w;
    float q = v.x * v.x + v.y * v.y + v.z * v.z + v.w * v.w;
#pragma unroll
    for (int o = 16; o; o >>= 1) {
        s += __shfl_xor_sync(0xFFFFFFFF, s, o);
        q += __shfl_xor_sync(0xFFFFFFFF, q, o);
    }
    __shared__ float ss[8], sq[8];
    int wid = threadIdx.x >> 5, lane = threadIdx.x & 31;
    if (lane == 0) { ss[wid] = s; sq[wid] = q; }
    __syncthreads();
    s = 0.f; q = 0.f;
#pragma unroll
    for (int i = 0; i < 8; i++) { s += ss[i]; q += sq[i]; }
    float mu  = s * (1.f / 1024.f);
    float var = q * (1.f / 1024.f) - mu * mu;
    float inv = rsqrtf(var + 1e-5f);
    float4 wv = ((const float4*)w)[threadIdx.x];
    float4 bv = ((const float4*)b)[threadIdx.x];
    float4 o;
    o.x = f2tf32f((v.x - mu) * inv * wv.x + bv.x);
    o.y = f2tf32f((v.y - mu) * inv * wv.y + bv.y);
    o.z = f2tf32f((v.z - mu) * inv * wv.z + bv.z);
    o.w = f2tf32f((v.w - mu) * inv * wv.w + bv.w);
    ((float4*)(y + (size_t)row * 1024))[threadIdx.x] = o;
}

// ---------------- tf32 mma GEMM: CTA 128x256, BK=16, 4 stages ----------------
// Per z: C[m][n] = epi( sum_k A[m][k] * Bt[n][k] ). A shared across z.
// mode 0: raw   1: sigmoid(acc+bias)   3: acc(+bias)+resid
// 512 thr = 16 warps (4m x 4n), warp tile 32x64.
#define NSTG  4
#define AST   20
#define AWRD  (128 * AST)           // A tile words
#define BWRD  (256 * AST)           // B tile words
#define STGW  (AWRD + BWRD)         // 7680 words / stage
#define GSMEM (NSTG * STGW * 4)     // 122880 bytes

struct GB { const float* Bt; const float* bias; const float* resid; float* C; int mode; };
struct GArgs { GB g[4]; };

__global__ __launch_bounds__(512, 1) void gemm_mma(const float* __restrict__ A,
                                                   GArgs ga, int K, int N) {
    extern __shared__ char smem[];
    uint32_t sbase = smem_u32(smem);

    GB gb = ga.g[blockIdx.z];
    const float* __restrict__ Bt = gb.Bt;

    int tid = threadIdx.x;
    int wid = tid >> 5, lane = tid & 31;
    int wm = wid & 3, wn = wid >> 2;
    int m0 = wm * 32, n0 = wn * 64;
    int grp = lane >> 2, ktid = lane & 3;
    int brow = blockIdx.y * 128, bcol = blockIdx.x * 256;

    // A: 128 rows x 16 words; thread -> row = tid>>2, colw = (tid&3)*4 (1 cp.async)
    int arow = tid >> 2, acw = (tid & 3) * 4;
    const float* gA = A + (size_t)(brow + arow) * K + acw;
    uint32_t dA = sbase + (uint32_t)(arow * AST + acw) * 4;
    // B: 256 rows x 16 words; thread -> row = tid>>1, colw = (tid&1)*8 (2 cp.async)
    int brw = tid >> 1, bcw = (tid & 1) * 8;
    const float* gB = Bt + (size_t)(bcol + brw) * K + bcw;
    uint32_t dB = sbase + (uint32_t)(AWRD + brw * AST + bcw) * 4;

    // ldmatrix per-lane addresses
    int l7 = lane & 7, lq = (lane >> 3) & 1, lh = lane >> 4;
    uint32_t aB = sbase + (uint32_t)(((m0 + lq * 8 + l7) * AST + lh * 4) * 4);
    uint32_t bB = sbase + (uint32_t)((AWRD + (n0 + lq * 8 + l7) * AST + lh * 4) * 4);

    float acc[2][8][4];
#pragma unroll
    for (int i = 0; i < 2; i++)
#pragma unroll
        for (int j = 0; j < 8; j++)
#pragma unroll
            for (int v = 0; v < 4; v++) acc[i][j][v] = 0.f;

    const int nk = K / 16;

#pragma unroll
    for (int p = 0; p < NSTG - 1; p++) {
        uint32_t o = (uint32_t)p * (STGW * 4);
        CP_ASYNC16(dA + o, gA + p * 16);
        CP_ASYNC16(dB + o, gB + p * 16);
        CP_ASYNC16(dB + o + 16, gB + p * 16 + 4);
        CP_COMMIT();
    }

    for (int kt = 0; kt < nk; kt++) {
        CP_WAIT2();
        __syncthreads();

        if (kt + NSTG - 1 < nk) {
            uint32_t o = (uint32_t)((kt + NSTG - 1) & (NSTG - 1)) * (STGW * 4);
            const float* a = gA + (kt + NSTG - 1) * 16;
            const float* b = gB + (kt + NSTG - 1) * 16;
            CP_ASYNC16(dA + o, a);
            CP_ASYNC16(dB + o, b);
            CP_ASYNC16(dB + o + 16, b + 4);
        }
        CP_COMMIT();

        uint32_t so = (uint32_t)(kt & (NSTG - 1)) * (STGW * 4);

#pragma unroll
        for (int ks = 0; ks < 2; ks++) {
            uint32_t af[2][4], bf[8][2];
#pragma unroll
            for (int mi = 0; mi < 2; mi++)
                LDSM4(af[mi][0], af[mi][1], af[mi][2], af[mi][3],
                      aB + so + (uint32_t)(mi * 16 * AST * 4) + (uint32_t)(ks * 32));
#pragma unroll
            for (int p = 0; p < 4; p++)
                LDSM4(bf[2 * p][0], bf[2 * p + 1][0], bf[2 * p][1], bf[2 * p + 1][1],
                      bB + so + (uint32_t)(p * 16 * AST * 4) + (uint32_t)(ks * 32));
#pragma unroll
            for (int mi = 0; mi < 2; mi++)
#pragma unroll
                for (int ni = 0; ni < 8; ni++)
                    MMA_TF32(acc[mi][ni], af[mi], bf[ni]);
        }
    }

    // ---------------- epilogue ----------------
    int mode = gb.mode;
    const float* bias = gb.bias;
    const float* resid = gb.resid;
    float* C = gb.C;
#pragma unroll
    for (int mi = 0; mi < 2; mi++) {
#pragma unroll
        for (int ni = 0; ni < 8; ni++) {
            int row = brow + m0 + mi * 16 + grp;
            int col = bcol + n0 + ni * 8 + ktid * 2;
            float b0v = 0.f, b1v = 0.f;
            if ((mode != 0) && bias) { b0v = bias[col]; b1v = bias[col + 1]; }
#pragma unroll
            for (int half = 0; half < 2; half++) {
                int r = row + half * 8;
                float v0 = acc[mi][ni][half * 2 + 0] + b0v;
                float v1 = acc[mi][ni][half * 2 + 1] + b1v;
                if (mode == 1) { v0 = sigm(v0); v1 = sigm(v1); }
                size_t off = (size_t)r * N + col;
                if (mode == 3) {
                    float2 rr = *(const float2*)(resid + off);
                    v0 += rr.x; v1 += rr.y;
                }
                float2 o; o.x = v0; o.y = v1;
                *(float2*)(C + off) = o;
            }
        }
    }
}

// ---------------- zi = tf32(b0 * b1) elementwise ----------------
__global__ __launch_bounds__(256) void gateprod(const float* __restrict__ b0,
                                                const float* __restrict__ b1,
                                                float* __restrict__ o) {
    int i = blockIdx.x * 256 + threadIdx.x;
    float4 a = ((const float4*)b0)[i];
    float4 b = ((const float4*)b1)[i];
    a.x = f2tf32f(a.x * b.x);
    a.y = f2tf32f(a.y * b.y);
    a.z = f2tf32f(a.z * b.z);
    a.w = f2tf32f(a.w * b.w);
    ((float4*)o)[i] = a;
}

// ---------------- chunked scan: h_t = r_t*h_{t-1} + yi_t,  yi = b0*b1 ----------------
__global__ __launch_bounds__(256) void scan_pass1(const float* __restrict__ b0,
                                                  const float* __restrict__ b1,
                                                  const float* __restrict__ rb,
                                                  float* __restrict__ Ac,
                                                  float* __restrict__ Sc) {
    int idx = blockIdx.x * 256 + threadIdx.x;
    int ch  = idx & 8191;
    int c   = idx >> 13;
    int b   = ch >> 11;
    int base = (b * 2048 + c * TCH) * 2048 + (ch & 2047);
    float A = 1.f, S = 0.f;
#pragma unroll 4
    for (int t = 0; t < TCH; t++) {
        float rr = rb[base];
        S = fmaf(rr, S, b0[base] * b1[base]);
        A *= rr;
        base += 2048;
    }
    Ac[idx] = A;
    Sc[idx] = S;
}

__global__ __launch_bounds__(256) void scan_pass2(const float* __restrict__ mem,
                                                  const float* __restrict__ Ac,
                                                  const float* __restrict__ Sc,
                                                  float* __restrict__ Hc,
                                                  float* __restrict__ memout) {
    int ch = blockIdx.x * 256 + threadIdx.x;
    float h = mem[ch];
#pragma unroll
    for (int c = 0; c < NCHUNK; c++) {
        int i = c * 8192 + ch;
        Hc[i] = h;
        h = fmaf(Ac[i], h, Sc[i]);
    }
    memout[ch] = h;
}

__global__ __launch_bounds__(256) void scan_pass3(const float* __restrict__ b0,
                                                  const float* __restrict__ b1,
                                                  const float* __restrict__ rb,
                                                  const float* __restrict__ og,
                                                  const float* __restrict__ Hc,
                                                  float* __restrict__ g) {
    int idx = blockIdx.x * 256 + threadIdx.x;
    int ch  = idx & 8191;
    int c   = idx >> 13;
    int b   = ch >> 11;
    int base = (b * 2048 + c * TCH) * 2048 + (ch & 2047);
    float h = Hc[idx];
#pragma unroll 4
    for (int t = 0; t < TCH; t++) {
        float rr = rb[base];
        h = fmaf(rr, h, b0[base] * b1[base]);
        float s = h / (1.f + fabsf(h));
        g[base] = f2tf32f(s * og[base]);
        base += 2048;
    }
}

// ---------------- host launch ----------------
extern "C" void kernel_launch(void* const* d_in, const int* in_sizes, int n_in,
                              void* d_out, int out_size) {
    const float* x    = (const float*)d_in[0];
    const float* mem  = (const float*)d_in[1];
    const float* ln1w = (const float*)d_in[2];
    const float* ln1b = (const float*)d_in[3];
    const float* wf   = (const float*)d_in[4];
    const float* wfb  = (const float*)d_in[5];
    const float* wi   = (const float*)d_in[6];
    const float* wig  = (const float*)d_in[7];
    const float* wigb = (const float*)d_in[8];
    const float* wog  = (const float*)d_in[9];
    const float* wogb = (const float*)d_in[10];
    const float* wo   = (const float*)d_in[11];
    const float* ln2w = (const float*)d_in[12];
    const float* ln2b = (const float*)d_in[13];
    const float* fwi  = (const float*)d_in[14];
    const float* fwg  = (const float*)d_in[15];
    const float* fwgb = (const float*)d_in[16];
    const float* fwo  = (const float*)d_in[17];
    const float* fwob = (const float*)d_in[18];
    float* out = (float*)d_out;

    float *y, *b0, *b1, *rb, *og, *g, *x2, *z, *Ac, *Sc, *Hc, *wT;
    cudaGetSymbolAddress((void**)&y,  g_y);
    cudaGetSymbolAddress((void**)&b0, g_b0);
    cudaGetSymbolAddress((void**)&b1, g_b1);
    cudaGetSymbolAddress((void**)&rb, g_r);
    cudaGetSymbolAddress((void**)&og, g_og);
    cudaGetSymbolAddress((void**)&g,  g_g);
    cudaGetSymbolAddress((void**)&x2, g_x2);
    cudaGetSymbolAddress((void**)&z,  g_z);
    cudaGetSymbolAddress((void**)&Ac, g_Ac);
    cudaGetSymbolAddress((void**)&Sc, g_Sc);
    cudaGetSymbolAddress((void**)&Hc, g_Hc);
    cudaGetSymbolAddress((void**)&wT, g_wT);

    cudaFuncSetAttribute(gemm_mma, cudaFuncAttributeMaxDynamicSharedMemorySize, GSMEM);

    float* wiT  = wT + 0 * WSLOT;
    float* wigT = wT + 1 * WSLOT;
    float* wfT  = wT + 2 * WSLOT;
    float* wogT = wT + 3 * WSLOT;
    float* woT  = wT + 4 * WSLOT;
    float* fwiT = wT + 5 * WSLOT;
    float* fwgT = wT + 6 * WSLOT;
    float* fwoT = wT + 7 * WSLOT;

    TArgs ta;
    ta.s[0] = wi;  ta.d[0] = wiT;  ta.K[0] = E_DIM; ta.N[0] = M_DIM;
    ta.s[1] = wig; ta.d[1] = wigT; ta.K[1] = E_DIM; ta.N[1] = M_DIM;
    ta.s[2] = wf;  ta.d[2] = wfT;  ta.K[2] = E_DIM; ta.N[2] = M_DIM;
    ta.s[3] = wog; ta.d[3] = wogT; ta.K[3] = E_DIM; ta.N[3] = M_DIM;
    ta.s[4] = wo;  ta.d[4] = woT;  ta.K[4] = M_DIM; ta.N[4] = E_DIM;
    ta.s[5] = fwi; ta.d[5] = fwiT; ta.K[5] = E_DIM; ta.N[5] = M_DIM;
    ta.s[6] = fwg; ta.d[6] = fwgT; ta.K[6] = E_DIM; ta.N[6] = M_DIM;
    ta.s[7] = fwo; ta.d[7] = fwoT; ta.K[7] = M_DIM; ta.N[7] = E_DIM;
    dim3 tg(WSLOT / (32 * 32), 8);
    tcvt8<<<tg, dim3(32, 8)>>>(ta);

    ln1024<<<R_ROWS, 256>>>(x, ln1w, ln1b, y);

    // 4 gate GEMMs in one launch (independent; yi formed in scan)
    {
        GArgs ga;
        ga.g[0] = { wiT,  nullptr, nullptr, b0, 0 };
        ga.g[1] = { wigT, wigb,    nullptr, b1, 1 };
        ga.g[2] = { wfT,  wfb,     nullptr, rb, 1 };
        ga.g[3] = { wogT, wogb,    nullptr, og, 1 };
        dim3 gr(M_DIM / 256, R_ROWS / 128, 4);
        gemm_mma<<<gr, 512, GSMEM>>>(y, ga, E_DIM, M_DIM);
    }

    scan_pass1<<<NCHUNK * 8192 / 256, 256>>>(b0, b1, rb, Ac, Sc);
    scan_pass2<<<8192 / 256, 256>>>(mem, Ac, Sc, Hc, out + (size_t)R_ROWS * E_DIM);
    scan_pass3<<<NCHUNK * 8192 / 256, 256>>>(b0, b1, rb, og, Hc, g);

    // x2 = x + g @ wo
    {
        GArgs ga;
        ga.g[0] = { woT, nullptr, x, x2, 3 };
        dim3 gr(E_DIM / 256, R_ROWS / 128, 1);
        gemm_mma<<<gr, 512, GSMEM>>>(g, ga, M_DIM, E_DIM);
    }

    ln1024<<<R_ROWS, 256>>>(x2, ln2w, ln2b, z);

    // FFN in+gate in one launch
    {
        GArgs ga;
        ga.g[0] = { fwiT, nullptr, nullptr, b0, 0 };
        ga.g[1] = { fwgT, fwgb,    nullptr, b1, 1 };
        dim3 gr(M_DIM / 256, R_ROWS / 128, 2);
        gemm_mma<<<gr, 512, GSMEM>>>(z, ga, E_DIM, M_DIM);
    }

    // zi = tf32(b0*b1) into g
    gateprod<<<R_ROWS * M_DIM / 4 / 256, 256>>>(b0, b1, g);

    // out = x2 + zi @ fwo + fwob
    {
        GArgs ga;
        ga.g[0] = { fwoT, fwob, x2, out, 3 };
        dim3 gr(E_DIM / 256, R_ROWS / 128, 1);
        gemm_mma<<<gr, 512, GSMEM>>>(g, ga, M_DIM, E_DIM);
    }
}

// round 11
// speedup vs baseline: 2.1149x; 1.8008x over previous
#include <cuda_runtime.h>
#include <cuda_fp16.h>
#include <cstdint>
#include <math.h>

// Sizes fixed: B=4, T=2048, E=1024, M=2048; R = B*T = 8192.
#define R_ROWS 8192
#define E_DIM  1024
#define M_DIM  2048
#define NCHUNK 16
#define TCH    128

// ---------------- scratch ----------------
__device__ float g_b0[R_ROWS * M_DIM];
__device__ float g_b1[R_ROWS * M_DIM];
__device__ float g_r [R_ROWS * M_DIM];
__device__ float g_og[R_ROWS * M_DIM];
__device__ float g_x2[R_ROWS * E_DIM];
__device__ float g_Ac[NCHUNK * 8192];
__device__ float g_Sc[NCHUNK * 8192];
__device__ float g_Hc[NCHUNK * 8192];
#define WSLOT (E_DIM * M_DIM)
__device__ __align__(256) __half g_wH[8 * WSLOT];      // transposed fp16 weights [N][K]
__device__ __align__(256) __half g_yh[R_ROWS * E_DIM]; // LN1 out (fp16)
__device__ __align__(256) __half g_zh[R_ROWS * E_DIM]; // LN2 out (fp16)
__device__ __align__(256) __half g_gh[R_ROWS * M_DIM]; // gate out (fp16)
__device__ __align__(256) __half g_zi[R_ROWS * M_DIM]; // FFN gated product (fp16)

__device__ __forceinline__ float sigm(float x) { return 1.f / (1.f + __expf(-x)); }

__device__ __forceinline__ uint32_t smem_u32(const void* p) {
    uint32_t a;
    asm("{ .reg .u64 t; cvta.to.shared.u64 t, %1; cvt.u32.u64 %0, t; }" : "=r"(a) : "l"(p));
    return a;
}

#define CP_ASYNC16(dst, src) asm volatile("cp.async.cg.shared.global [%0], [%1], 16;" :: "r"(dst), "l"(src))
#define CP_COMMIT()          asm volatile("cp.async.commit_group;" ::: "memory")
#define CP_WAIT2()           asm volatile("cp.async.wait_group 2;" ::: "memory")

#define LDSM4(r0, r1, r2, r3, addr)                                            \
    asm volatile("ldmatrix.sync.aligned.m8n8.x4.shared.b16 {%0,%1,%2,%3}, [%4];" \
        : "=r"(r0), "=r"(r1), "=r"(r2), "=r"(r3) : "r"(addr))

#define MMA_F16(c, a, b)                                                       \
    asm volatile("mma.sync.aligned.m16n8k16.row.col.f32.f16.f16.f32 "          \
        "{%0,%1,%2,%3}, {%4,%5,%6,%7}, {%8,%9}, {%0,%1,%2,%3};"                \
        : "+f"((c)[0]), "+f"((c)[1]), "+f"((c)[2]), "+f"((c)[3])               \
        : "r"((a)[0]), "r"((a)[1]), "r"((a)[2]), "r"((a)[3]),                  \
          "r"((b)[0]), "r"((b)[1]))

__device__ __forceinline__ uint32_t pack_h2(float a, float b) {
    __half2 h = __floats2half2_rn(a, b);
    return *reinterpret_cast<uint32_t*>(&h);
}

// ---------------- batched fused transpose + fp16 convert ----------------
struct TArgs { const float* s[8]; __half* d[8]; int K[8]; int N[8]; };
__global__ __launch_bounds__(256) void tcvt8(TArgs a) {
    __shared__ float t[32][33];
    int w = blockIdx.y;
    int K = a.K[w], N = a.N[w];
    int nb = N >> 5;
    int bx = (blockIdx.x % nb) * 32;
    int by = (blockIdx.x / nb) * 32;
    const float* src = a.s[w];
    __half* dst = a.d[w];
#pragma unroll
    for (int i = threadIdx.y; i < 32; i += 8)
        t[i][threadIdx.x] = src[(size_t)(by + i) * N + bx + threadIdx.x];
    __syncthreads();
#pragma unroll
    for (int i = threadIdx.y; i < 32; i += 8)
        dst[(size_t)(bx + i) * K + by + threadIdx.x] = __float2half_rn(t[threadIdx.x][i]);
}

// ---------------- LayerNorm (rows of 1024), fp16 output ----------------
__global__ __launch_bounds__(256) void ln1024(const float* __restrict__ x,
                                              const float* __restrict__ w,
                                              const float* __restrict__ b,
                                              __half* __restrict__ y) {
    int row = blockIdx.x;
    const float4* xr = (const float4*)(x + (size_t)row * 1024);
    float4 v = xr[threadIdx.x];
    float s = v.x + v.y + v.z + v.w;
    float q = v.x * v.x + v.y * v.y + v.z * v.z + v.w * v.w;
#pragma unroll
    for (int o = 16; o; o >>= 1) {
        s += __shfl_xor_sync(0xFFFFFFFF, s, o);
        q += __shfl_xor_sync(0xFFFFFFFF, q, o);
    }
    __shared__ float ss[8], sq[8];
    int wid = threadIdx.x >> 5, lane = threadIdx.x & 31;
    if (lane == 0) { ss[wid] = s; sq[wid] = q; }
    __syncthreads();
    s = 0.f; q = 0.f;
#pragma unroll
    for (int i = 0; i < 8; i++) { s += ss[i]; q += sq[i]; }
    float mu  = s * (1.f / 1024.f);
    float var = q * (1.f / 1024.f) - mu * mu;
    float inv = rsqrtf(var + 1e-5f);
    float4 wv = ((const float4*)w)[threadIdx.x];
    float4 bv = ((const float4*)b)[threadIdx.x];
    uint2 pk;
    pk.x = pack_h2((v.x - mu) * inv * wv.x + bv.x, (v.y - mu) * inv * wv.y + bv.y);
    pk.y = pack_h2((v.z - mu) * inv * wv.z + bv.z, (v.w - mu) * inv * wv.w + bv.w);
    ((uint2*)(y + (size_t)row * 1024))[threadIdx.x] = pk;
}

// ---------------- fp16 mma GEMM: CTA 128x256, BK=32(halves), 4 stages ----------------
// Per z: C[m][n] = epi( sum_k A[m][k] * Bt[n][k] ). A:[M,K] half rm, Bt:[N,K] half rm.
// mode 0: raw   1: sigmoid(acc+bias)   3: acc(+bias)+resid
// 512 thr = 16 warps (4m x 4n), warp tile 32x64.
#define NSTG  4
#define ASTH  40                    // halves per row (32 + 8 pad) -> conflict-free ldmatrix
#define AWRDH (128 * ASTH)          // A tile halves
#define BWRDH (256 * ASTH)          // B tile halves
#define STGH  (AWRDH + BWRDH)       // 15360 halves / stage
#define GSMEM (NSTG * STGH * 2)     // 122880 bytes

struct GB { const __half* Bt; const float* bias; const float* resid; float* C; int mode; };
struct GArgs { GB g[4]; };

__global__ __launch_bounds__(512, 1) void gemm_mma(const __half* __restrict__ A,
                                                   GArgs ga, int K, int N) {
    extern __shared__ char smem[];
    uint32_t sbase = smem_u32(smem);

    GB gb = ga.g[blockIdx.z];
    const __half* __restrict__ Bt = gb.Bt;

    int tid = threadIdx.x;
    int wid = tid >> 5, lane = tid & 31;
    int wm = wid & 3, wn = wid >> 2;
    int m0 = wm * 32, n0 = wn * 64;
    int grp = lane >> 2, ktid = lane & 3;
    int brow = blockIdx.y * 128, bcol = blockIdx.x * 256;

    // A: 128 rows x 32 halves; 4 chunks(16B)/row; thread -> row = tid>>2, chunk = tid&3
    int arow = tid >> 2, ach = tid & 3;
    const __half* gA = A + (size_t)(brow + arow) * K + ach * 8;
    uint32_t dA = sbase + (uint32_t)(arow * ASTH + ach * 8) * 2;
    // B: 256 rows x 32 halves; 2 chunk-pairs/row; thread -> row = tid>>1
    int brw = tid >> 1, bch = tid & 1;
    const __half* gB = Bt + (size_t)(bcol + brw) * K + bch * 16;
    uint32_t dB = sbase + (uint32_t)(AWRDH + brw * ASTH + bch * 16) * 2;

    // ldmatrix lane addresses
    int l7 = lane & 7;
    int aq = (lane >> 3) & 1, ah = lane >> 4;       // A: +8 rows, +16B col
    int bq = lane >> 4, bh = (lane >> 3) & 1;       // B: +8 rows, +16B col (swapped)
    uint32_t aB = sbase + (uint32_t)((m0 + aq * 8 + l7) * ASTH) * 2 + (uint32_t)(ah * 16);
    uint32_t bB = sbase + (uint32_t)(AWRDH + (n0 + bq * 8 + l7) * ASTH) * 2 + (uint32_t)(bh * 16);

    float acc[2][8][4];
#pragma unroll
    for (int i = 0; i < 2; i++)
#pragma unroll
        for (int j = 0; j < 8; j++)
#pragma unroll
            for (int v = 0; v < 4; v++) acc[i][j][v] = 0.f;

    const int nk = K / 32;

#pragma unroll
    for (int p = 0; p < NSTG - 1; p++) {
        uint32_t o = (uint32_t)p * (STGH * 2);
        CP_ASYNC16(dA + o, gA + p * 32);
        CP_ASYNC16(dB + o, gB + p * 32);
        CP_ASYNC16(dB + o + 16, gB + p * 32 + 8);
        CP_COMMIT();
    }

    for (int kt = 0; kt < nk; kt++) {
        CP_WAIT2();
        __syncthreads();

        if (kt + NSTG - 1 < nk) {
            uint32_t o = (uint32_t)((kt + NSTG - 1) & (NSTG - 1)) * (STGH * 2);
            const __half* a = gA + (kt + NSTG - 1) * 32;
            const __half* b = gB + (kt + NSTG - 1) * 32;
            CP_ASYNC16(dA + o, a);
            CP_ASYNC16(dB + o, b);
            CP_ASYNC16(dB + o + 16, b + 8);
        }
        CP_COMMIT();

        uint32_t so = (uint32_t)(kt & (NSTG - 1)) * (STGH * 2);

#pragma unroll
        for (int ks = 0; ks < 2; ks++) {        // two k16 steps per 32-half tile
            uint32_t af[2][4], bf[8][2];
#pragma unroll
            for (int mi = 0; mi < 2; mi++)
                LDSM4(af[mi][0], af[mi][1], af[mi][2], af[mi][3],
                      aB + so + (uint32_t)(mi * 16 * ASTH * 2) + (uint32_t)(ks * 32));
#pragma unroll
            for (int p = 0; p < 4; p++)
                LDSM4(bf[2 * p][0], bf[2 * p][1], bf[2 * p + 1][0], bf[2 * p + 1][1],
                      bB + so + (uint32_t)(p * 16 * ASTH * 2) + (uint32_t)(ks * 32));
#pragma unroll
            for (int mi = 0; mi < 2; mi++)
#pragma unroll
                for (int ni = 0; ni < 8; ni++)
                    MMA_F16(acc[mi][ni], af[mi], bf[ni]);
        }
    }

    // ---------------- epilogue ----------------
    int mode = gb.mode;
    const float* bias = gb.bias;
    const float* resid = gb.resid;
    float* C = gb.C;
#pragma unroll
    for (int mi = 0; mi < 2; mi++) {
#pragma unroll
        for (int ni = 0; ni < 8; ni++) {
            int row = brow + m0 + mi * 16 + grp;
            int col = bcol + n0 + ni * 8 + ktid * 2;
            float b0v = 0.f, b1v = 0.f;
            if ((mode != 0) && bias) { b0v = bias[col]; b1v = bias[col + 1]; }
#pragma unroll
            for (int half = 0; half < 2; half++) {
                int r = row + half * 8;
                float v0 = acc[mi][ni][half * 2 + 0] + b0v;
                float v1 = acc[mi][ni][half * 2 + 1] + b1v;
                if (mode == 1) { v0 = sigm(v0); v1 = sigm(v1); }
                size_t off = (size_t)r * N + col;
                if (mode == 3) {
                    float2 rr = *(const float2*)(resid + off);
                    v0 += rr.x; v1 += rr.y;
                }
                float2 o; o.x = v0; o.y = v1;
                *(float2*)(C + off) = o;
            }
        }
    }
}

// ---------------- zi = fp16(b0 * b1) elementwise ----------------
__global__ __launch_bounds__(256) void gateprod(const float* __restrict__ b0,
                                                const float* __restrict__ b1,
                                                __half* __restrict__ o) {
    int i = blockIdx.x * 256 + threadIdx.x;
    float4 a = ((const float4*)b0)[i];
    float4 b = ((const float4*)b1)[i];
    uint2 pk;
    pk.x = pack_h2(a.x * b.x, a.y * b.y);
    pk.y = pack_h2(a.z * b.z, a.w * b.w);
    ((uint2*)o)[i] = pk;
}

// ---------------- chunked scan: h_t = r_t*h_{t-1} + yi_t,  yi = b0*b1 ----------------
__global__ __launch_bounds__(256) void scan_pass1(const float* __restrict__ b0,
                                                  const float* __restrict__ b1,
                                                  const float* __restrict__ rb,
                                                  float* __restrict__ Ac,
                                                  float* __restrict__ Sc) {
    int idx = blockIdx.x * 256 + threadIdx.x;
    int ch  = idx & 8191;
    int c   = idx >> 13;
    int b   = ch >> 11;
    int base = (b * 2048 + c * TCH) * 2048 + (ch & 2047);
    float A = 1.f, S = 0.f;
#pragma unroll 4
    for (int t = 0; t < TCH; t++) {
        float rr = rb[base];
        S = fmaf(rr, S, b0[base] * b1[base]);
        A *= rr;
        base += 2048;
    }
    Ac[idx] = A;
    Sc[idx] = S;
}

__global__ __launch_bounds__(256) void scan_pass2(const float* __restrict__ mem,
                                                  const float* __restrict__ Ac,
                                                  const float* __restrict__ Sc,
                                                  float* __restrict__ Hc,
                                                  float* __restrict__ memout) {
    int ch = blockIdx.x * 256 + threadIdx.x;
    float h = mem[ch];
#pragma unroll
    for (int c = 0; c < NCHUNK; c++) {
        int i = c * 8192 + ch;
        Hc[i] = h;
        h = fmaf(Ac[i], h, Sc[i]);
    }
    memout[ch] = h;
}

__global__ __launch_bounds__(256) void scan_pass3(const float* __restrict__ b0,
                                                  const float* __restrict__ b1,
                                                  const float* __restrict__ rb,
                                                  const float* __restrict__ og,
                                                  const float* __restrict__ Hc,
                                                  __half* __restrict__ g) {
    int idx = blockIdx.x * 256 + threadIdx.x;
    int ch  = idx & 8191;
    int c   = idx >> 13;
    int b   = ch >> 11;
    int base = (b * 2048 + c * TCH) * 2048 + (ch & 2047);
    float h = Hc[idx];
#pragma unroll 4
    for (int t = 0; t < TCH; t++) {
        float rr = rb[base];
        h = fmaf(rr, h, b0[base] * b1[base]);
        float s = h / (1.f + fabsf(h));
        g[base] = __float2half_rn(s * og[base]);
        base += 2048;
    }
}

// ---------------- host launch ----------------
extern "C" void kernel_launch(void* const* d_in, const int* in_sizes, int n_in,
                              void* d_out, int out_size) {
    const float* x    = (const float*)d_in[0];
    const float* mem  = (const float*)d_in[1];
    const float* ln1w = (const float*)d_in[2];
    const float* ln1b = (const float*)d_in[3];
    const float* wf   = (const float*)d_in[4];
    const float* wfb  = (const float*)d_in[5];
    const float* wi   = (const float*)d_in[6];
    const float* wig  = (const float*)d_in[7];
    const float* wigb = (const float*)d_in[8];
    const float* wog  = (const float*)d_in[9];
    const float* wogb = (const float*)d_in[10];
    const float* wo   = (const float*)d_in[11];
    const float* ln2w = (const float*)d_in[12];
    const float* ln2b = (const float*)d_in[13];
    const float* fwi  = (const float*)d_in[14];
    const float* fwg  = (const float*)d_in[15];
    const float* fwgb = (const float*)d_in[16];
    const float* fwo  = (const float*)d_in[17];
    const float* fwob = (const float*)d_in[18];
    float* out = (float*)d_out;

    float *b0, *b1, *rb, *og, *x2, *Ac, *Sc, *Hc;
    __half *wH, *yh, *zh, *gh, *zi;
    cudaGetSymbolAddress((void**)&b0, g_b0);
    cudaGetSymbolAddress((void**)&b1, g_b1);
    cudaGetSymbolAddress((void**)&rb, g_r);
    cudaGetSymbolAddress((void**)&og, g_og);
    cudaGetSymbolAddress((void**)&x2, g_x2);
    cudaGetSymbolAddress((void**)&Ac, g_Ac);
    cudaGetSymbolAddress((void**)&Sc, g_Sc);
    cudaGetSymbolAddress((void**)&Hc, g_Hc);
    cudaGetSymbolAddress((void**)&wH, g_wH);
    cudaGetSymbolAddress((void**)&yh, g_yh);
    cudaGetSymbolAddress((void**)&zh, g_zh);
    cudaGetSymbolAddress((void**)&gh, g_gh);
    cudaGetSymbolAddress((void**)&zi, g_zi);

    cudaFuncSetAttribute(gemm_mma, cudaFuncAttributeMaxDynamicSharedMemorySize, GSMEM);

    __half* wiT  = wH + 0 * WSLOT;
    __half* wigT = wH + 1 * WSLOT;
    __half* wfT  = wH + 2 * WSLOT;
    __half* wogT = wH + 3 * WSLOT;
    __half* woT  = wH + 4 * WSLOT;
    __half* fwiT = wH + 5 * WSLOT;
    __half* fwgT = wH + 6 * WSLOT;
    __half* fwoT = wH + 7 * WSLOT;

    TArgs ta;
    ta.s[0] = wi;  ta.d[0] = wiT;  ta.K[0] = E_DIM; ta.N[0] = M_DIM;
    ta.s[1] = wig; ta.d[1] = wigT; ta.K[1] = E_DIM; ta.N[1] = M_DIM;
    ta.s[2] = wf;  ta.d[2] = wfT;  ta.K[2] = E_DIM; ta.N[2] = M_DIM;
    ta.s[3] = wog; ta.d[3] = wogT; ta.K[3] = E_DIM; ta.N[3] = M_DIM;
    ta.s[4] = wo;  ta.d[4] = woT;  ta.K[4] = M_DIM; ta.N[4] = E_DIM;
    ta.s[5] = fwi; ta.d[5] = fwiT; ta.K[5] = E_DIM; ta.N[5] = M_DIM;
    ta.s[6] = fwg; ta.d[6] = fwgT; ta.K[6] = E_DIM; ta.N[6] = M_DIM;
    ta.s[7] = fwo; ta.d[7] = fwoT; ta.K[7] = M_DIM; ta.N[7] = E_DIM;
    dim3 tg(WSLOT / (32 * 32), 8);
    tcvt8<<<tg, dim3(32, 8)>>>(ta);

    ln1024<<<R_ROWS, 256>>>(x, ln1w, ln1b, yh);

    // 4 gate GEMMs in one launch
    {
        GArgs ga;
        ga.g[0] = { wiT,  nullptr, nullptr, b0, 0 };
        ga.g[1] = { wigT, wigb,    nullptr, b1, 1 };
        ga.g[2] = { wfT,  wfb,     nullptr, rb, 1 };
        ga.g[3] = { wogT, wogb,    nullptr, og, 1 };
        dim3 gr(M_DIM / 256, R_ROWS / 128, 4);
        gemm_mma<<<gr, 512, GSMEM>>>(yh, ga, E_DIM, M_DIM);
    }

    scan_pass1<<<NCHUNK * 8192 / 256, 256>>>(b0, b1, rb, Ac, Sc);
    scan_pass2<<<8192 / 256, 256>>>(mem, Ac, Sc, Hc, out + (size_t)R_ROWS * E_DIM);
    scan_pass3<<<NCHUNK * 8192 / 256, 256>>>(b0, b1, rb, og, Hc, gh);

    // x2 = x + g @ wo
    {
        GArgs ga;
        ga.g[0] = { woT, nullptr, x, x2, 3 };
        dim3 gr(E_DIM / 256, R_ROWS / 128, 1);
        gemm_mma<<<gr, 512, GSMEM>>>(gh, ga, M_DIM, E_DIM);
    }

    ln1024<<<R_ROWS, 256>>>(x2, ln2w, ln2b, zh);

    // FFN in+gate in one launch
    {
        GArgs ga;
        ga.g[0] = { fwiT, nullptr, nullptr, b0, 0 };
        ga.g[1] = { fwgT, fwgb,    nullptr, b1, 1 };
        dim3 gr(M_DIM / 256, R_ROWS / 128, 2);
        gemm_mma<<<gr, 512, GSMEM>>>(zh, ga, E_DIM, M_DIM);
    }

    // zi = fp16(b0*b1)
    gateprod<<<R_ROWS * M_DIM / 4 / 256, 256>>>(b0, b1, zi);

    // out = x2 + zi @ fwo + fwob
    {
        GArgs ga;
        ga.g[0] = { fwoT, fwob, x2, out, 3 };
        dim3 gr(E_DIM / 256, R_ROWS / 128, 1);
        gemm_mma<<<gr, 512, GSMEM>>>(zi, ga, M_DIM, E_DIM);
    }
}

// round 12
// speedup vs baseline: 2.1712x; 1.0266x over previous
#include <cuda_runtime.h>
#include <cuda_fp16.h>
#include <cstdint>
#include <math.h>

// Sizes fixed: B=4, T=2048, E=1024, M=2048; R = B*T = 8192.
#define R_ROWS 8192
#define E_DIM  1024
#define M_DIM  2048
#define NCHUNK 16
#define TCH    128

// ---------------- scratch ----------------
__device__ float g_x2[R_ROWS * E_DIM];
__device__ float g_Ac[NCHUNK * 8192];
__device__ float g_Sc[NCHUNK * 8192];
__device__ float g_Hc[NCHUNK * 8192];
#define WSLOT (E_DIM * M_DIM)
__device__ __align__(256) __half g_wH[8 * WSLOT];      // transposed fp16 weights [N][K]
__device__ __align__(256) __half g_yh[R_ROWS * E_DIM]; // LN1 out
__device__ __align__(256) __half g_zh[R_ROWS * E_DIM]; // LN2 out
__device__ __align__(256) __half g_gh[R_ROWS * M_DIM]; // gate out
__device__ __align__(256) __half g_zi[R_ROWS * M_DIM]; // FFN gated product
__device__ __align__(256) __half g_b0[R_ROWS * M_DIM]; // raw y@wi / z@fwi
__device__ __align__(256) __half g_b1[R_ROWS * M_DIM]; // sigmoid gate
__device__ __align__(256) __half g_r [R_ROWS * M_DIM]; // forget gate
__device__ __align__(256) __half g_og[R_ROWS * M_DIM]; // output gate

__device__ __forceinline__ float sigm(float x) { return 1.f / (1.f + __expf(-x)); }

__device__ __forceinline__ uint32_t smem_u32(const void* p) {
    uint32_t a;
    asm("{ .reg .u64 t; cvta.to.shared.u64 t, %1; cvt.u32.u64 %0, t; }" : "=r"(a) : "l"(p));
    return a;
}

#define CP_ASYNC16(dst, src) asm volatile("cp.async.cg.shared.global [%0], [%1], 16;" :: "r"(dst), "l"(src))
#define CP_COMMIT()          asm volatile("cp.async.commit_group;" ::: "memory")
#define CP_WAIT2()           asm volatile("cp.async.wait_group 2;" ::: "memory")

#define LDSM4(r0, r1, r2, r3, addr)                                            \
    asm volatile("ldmatrix.sync.aligned.m8n8.x4.shared.b16 {%0,%1,%2,%3}, [%4];" \
        : "=r"(r0), "=r"(r1), "=r"(r2), "=r"(r3) : "r"(addr))

#define MMA_F16(c, a, b)                                                       \
    asm volatile("mma.sync.aligned.m16n8k16.row.col.f32.f16.f16.f32 "          \
        "{%0,%1,%2,%3}, {%4,%5,%6,%7}, {%8,%9}, {%0,%1,%2,%3};"                \
        : "+f"((c)[0]), "+f"((c)[1]), "+f"((c)[2]), "+f"((c)[3])               \
        : "r"((a)[0]), "r"((a)[1]), "r"((a)[2]), "r"((a)[3]),                  \
          "r"((b)[0]), "r"((b)[1]))

__device__ __forceinline__ uint32_t pack_h2(float a, float b) {
    __half2 h = __floats2half2_rn(a, b);
    return *reinterpret_cast<uint32_t*>(&h);
}

// ---------------- batched fused transpose + fp16 convert ----------------
struct TArgs { const float* s[8]; __half* d[8]; int K[8]; int N[8]; };
__global__ __launch_bounds__(256) void tcvt8(TArgs a) {
    __shared__ float t[32][33];
    int w = blockIdx.y;
    int K = a.K[w], N = a.N[w];
    int nb = N >> 5;
    int bx = (blockIdx.x % nb) * 32;
    int by = (blockIdx.x / nb) * 32;
    const float* src = a.s[w];
    __half* dst = a.d[w];
#pragma unroll
    for (int i = threadIdx.y; i < 32; i += 8)
        t[i][threadIdx.x] = src[(size_t)(by + i) * N + bx + threadIdx.x];
    __syncthreads();
#pragma unroll
    for (int i = threadIdx.y; i < 32; i += 8)
        dst[(size_t)(bx + i) * K + by + threadIdx.x] = __float2half_rn(t[threadIdx.x][i]);
}

// ---------------- LayerNorm (rows of 1024), fp16 output ----------------
__global__ __launch_bounds__(256) void ln1024(const float* __restrict__ x,
                                              const float* __restrict__ w,
                                              const float* __restrict__ b,
                                              __half* __restrict__ y) {
    int row = blockIdx.x;
    const float4* xr = (const float4*)(x + (size_t)row * 1024);
    float4 v = xr[threadIdx.x];
    float s = v.x + v.y + v.z + v.w;
    float q = v.x * v.x + v.y * v.y + v.z * v.z + v.w * v.w;
#pragma unroll
    for (int o = 16; o; o >>= 1) {
        s += __shfl_xor_sync(0xFFFFFFFF, s, o);
        q += __shfl_xor_sync(0xFFFFFFFF, q, o);
    }
    __shared__ float ss[8], sq[8];
    int wid = threadIdx.x >> 5, lane = threadIdx.x & 31;
    if (lane == 0) { ss[wid] = s; sq[wid] = q; }
    __syncthreads();
    s = 0.f; q = 0.f;
#pragma unroll
    for (int i = 0; i < 8; i++) { s += ss[i]; q += sq[i]; }
    float mu  = s * (1.f / 1024.f);
    float var = q * (1.f / 1024.f) - mu * mu;
    float inv = rsqrtf(var + 1e-5f);
    float4 wv = ((const float4*)w)[threadIdx.x];
    float4 bv = ((const float4*)b)[threadIdx.x];
    uint2 pk;
    pk.x = pack_h2((v.x - mu) * inv * wv.x + bv.x, (v.y - mu) * inv * wv.y + bv.y);
    pk.y = pack_h2((v.z - mu) * inv * wv.z + bv.z, (v.w - mu) * inv * wv.w + bv.w);
    ((uint2*)(y + (size_t)row * 1024))[threadIdx.x] = pk;
}

// ---------------- fp16 mma GEMM: CTA 128x256, BK=32(halves), 4 stages ----------------
// Per z: C[m][n] = epi( sum_k A[m][k] * Bt[n][k] ). A:[M,K] half rm, Bt:[N,K] half rm.
// mode 0: raw -> fp16   1: sigmoid(acc+bias) -> fp16   3: acc(+bias)+resid -> fp32
// 512 thr = 16 warps (4m x 4n), warp tile 32x64.
#define NSTG  4
#define ASTH  40
#define AWRDH (128 * ASTH)
#define BWRDH (256 * ASTH)
#define STGH  (AWRDH + BWRDH)
#define GSMEM (NSTG * STGH * 2)     // 122880 bytes

struct GB { const __half* Bt; const float* bias; const float* resid; void* C; int mode; };
struct GArgs { GB g[4]; };

__global__ __launch_bounds__(512, 1) void gemm_mma(const __half* __restrict__ A,
                                                   GArgs ga, int K, int N) {
    extern __shared__ char smem[];
    uint32_t sbase = smem_u32(smem);

    GB gb = ga.g[blockIdx.z];
    const __half* __restrict__ Bt = gb.Bt;

    int tid = threadIdx.x;
    int wid = tid >> 5, lane = tid & 31;
    int wm = wid & 3, wn = wid >> 2;
    int m0 = wm * 32, n0 = wn * 64;
    int grp = lane >> 2, ktid = lane & 3;
    int brow = blockIdx.y * 128, bcol = blockIdx.x * 256;

    int arow = tid >> 2, ach = tid & 3;
    const __half* gA = A + (size_t)(brow + arow) * K + ach * 8;
    uint32_t dA = sbase + (uint32_t)(arow * ASTH + ach * 8) * 2;
    int brw = tid >> 1, bch = tid & 1;
    const __half* gB = Bt + (size_t)(bcol + brw) * K + bch * 16;
    uint32_t dB = sbase + (uint32_t)(AWRDH + brw * ASTH + bch * 16) * 2;

    int l7 = lane & 7;
    int aq = (lane >> 3) & 1, ah = lane >> 4;
    int bq = lane >> 4, bh = (lane >> 3) & 1;
    uint32_t aB = sbase + (uint32_t)((m0 + aq * 8 + l7) * ASTH) * 2 + (uint32_t)(ah * 16);
    uint32_t bB = sbase + (uint32_t)(AWRDH + (n0 + bq * 8 + l7) * ASTH) * 2 + (uint32_t)(bh * 16);

    float acc[2][8][4];
#pragma unroll
    for (int i = 0; i < 2; i++)
#pragma unroll
        for (int j = 0; j < 8; j++)
#pragma unroll
            for (int v = 0; v < 4; v++) acc[i][j][v] = 0.f;

    const int nk = K / 32;

#pragma unroll
    for (int p = 0; p < NSTG - 1; p++) {
        uint32_t o = (uint32_t)p * (STGH * 2);
        CP_ASYNC16(dA + o, gA + p * 32);
        CP_ASYNC16(dB + o, gB + p * 32);
        CP_ASYNC16(dB + o + 16, gB + p * 32 + 8);
        CP_COMMIT();
    }

    for (int kt = 0; kt < nk; kt++) {
        CP_WAIT2();
        __syncthreads();

        if (kt + NSTG - 1 < nk) {
            uint32_t o = (uint32_t)((kt + NSTG - 1) & (NSTG - 1)) * (STGH * 2);
            const __half* a = gA + (kt + NSTG - 1) * 32;
            const __half* b = gB + (kt + NSTG - 1) * 32;
            CP_ASYNC16(dA + o, a);
            CP_ASYNC16(dB + o, b);
            CP_ASYNC16(dB + o + 16, b + 8);
        }
        CP_COMMIT();

        uint32_t so = (uint32_t)(kt & (NSTG - 1)) * (STGH * 2);

#pragma unroll
        for (int ks = 0; ks < 2; ks++) {
            uint32_t af[2][4], bf[8][2];
#pragma unroll
            for (int mi = 0; mi < 2; mi++)
                LDSM4(af[mi][0], af[mi][1], af[mi][2], af[mi][3],
                      aB + so + (uint32_t)(mi * 16 * ASTH * 2) + (uint32_t)(ks * 32));
#pragma unroll
            for (int p = 0; p < 4; p++)
                LDSM4(bf[2 * p][0], bf[2 * p][1], bf[2 * p + 1][0], bf[2 * p + 1][1],
                      bB + so + (uint32_t)(p * 16 * ASTH * 2) + (uint32_t)(ks * 32));
#pragma unroll
            for (int mi = 0; mi < 2; mi++)
#pragma unroll
                for (int ni = 0; ni < 8; ni++)
                    MMA_F16(acc[mi][ni], af[mi], bf[ni]);
        }
    }

    // ---------------- epilogue ----------------
    int mode = gb.mode;
    const float* bias = gb.bias;
    const float* resid = gb.resid;
#pragma unroll
    for (int mi = 0; mi < 2; mi++) {
#pragma unroll
        for (int ni = 0; ni < 8; ni++) {
            int row = brow + m0 + mi * 16 + grp;
            int col = bcol + n0 + ni * 8 + ktid * 2;
            float b0v = 0.f, b1v = 0.f;
            if ((mode != 0) && bias) { b0v = bias[col]; b1v = bias[col + 1]; }
#pragma unroll
            for (int half = 0; half < 2; half++) {
                int r = row + half * 8;
                float v0 = acc[mi][ni][half * 2 + 0] + b0v;
                float v1 = acc[mi][ni][half * 2 + 1] + b1v;
                size_t off = (size_t)r * N + col;
                if (mode == 3) {
                    float2 rr = *(const float2*)(resid + off);
                    float2 o; o.x = v0 + rr.x; o.y = v1 + rr.y;
                    *(float2*)((float*)gb.C + off) = o;
                } else {
                    if (mode == 1) { v0 = sigm(v0); v1 = sigm(v1); }
                    uint32_t pk = pack_h2(v0, v1);
                    *(uint32_t*)((__half*)gb.C + off) = pk;
                }
            }
        }
    }
}

// ---------------- zi = fp16(b0 * b1) elementwise (half in/out) ----------------
__global__ __launch_bounds__(256) void gateprod(const __half2* __restrict__ b0,
                                                const __half2* __restrict__ b1,
                                                __half2* __restrict__ o) {
    int i = blockIdx.x * 256 + threadIdx.x;
    uint2 pa = ((const uint2*)b0)[i];
    uint2 pb = ((const uint2*)b1)[i];
    float2 a0 = __half22float2(*(__half2*)&pa.x), a1 = __half22float2(*(__half2*)&pa.y);
    float2 c0 = __half22float2(*(__half2*)&pb.x), c1 = __half22float2(*(__half2*)&pb.y);
    uint2 pk;
    pk.x = pack_h2(a0.x * c0.x, a0.y * c0.y);
    pk.y = pack_h2(a1.x * c1.x, a1.y * c1.y);
    ((uint2*)o)[i] = pk;
}

// ---------------- chunked scan: h_t = r_t*h_{t-1} + yi_t,  yi = b0*b1 (half inputs) ----------------
__global__ __launch_bounds__(256) void scan_pass1(const __half* __restrict__ b0,
                                                  const __half* __restrict__ b1,
                                                  const __half* __restrict__ rb,
                                                  float* __restrict__ Ac,
                                                  float* __restrict__ Sc) {
    int idx = blockIdx.x * 256 + threadIdx.x;
    int ch  = idx & 8191;
    int c   = idx >> 13;
    int b   = ch >> 11;
    int base = (b * 2048 + c * TCH) * 2048 + (ch & 2047);
    float A = 1.f, S = 0.f;
#pragma unroll 4
    for (int t = 0; t < TCH; t++) {
        float rr = __half2float(rb[base]);
        float yi = __half2float(b0[base]) * __half2float(b1[base]);
        S = fmaf(rr, S, yi);
        A *= rr;
        base += 2048;
    }
    Ac[idx] = A;
    Sc[idx] = S;
}

__global__ __launch_bounds__(256) void scan_pass2(const float* __restrict__ mem,
                                                  const float* __restrict__ Ac,
                                                  const float* __restrict__ Sc,
                                                  float* __restrict__ Hc,
                                                  float* __restrict__ memout) {
    int ch = blockIdx.x * 256 + threadIdx.x;
    float h = mem[ch];
#pragma unroll
    for (int c = 0; c < NCHUNK; c++) {
        int i = c * 8192 + ch;
        Hc[i] = h;
        h = fmaf(Ac[i], h, Sc[i]);
    }
    memout[ch] = h;
}

__global__ __launch_bounds__(256) void scan_pass3(const __half* __restrict__ b0,
                                                  const __half* __restrict__ b1,
                                                  const __half* __restrict__ rb,
                                                  const __half* __restrict__ og,
                                                  const float* __restrict__ Hc,
                                                  __half* __restrict__ g) {
    int idx = blockIdx.x * 256 + threadIdx.x;
    int ch  = idx & 8191;
    int c   = idx >> 13;
    int b   = ch >> 11;
    int base = (b * 2048 + c * TCH) * 2048 + (ch & 2047);
    float h = Hc[idx];
#pragma unroll 4
    for (int t = 0; t < TCH; t++) {
        float rr = __half2float(rb[base]);
        float yi = __half2float(b0[base]) * __half2float(b1[base]);
        h = fmaf(rr, h, yi);
        float s = h / (1.f + fabsf(h));
        g[base] = __float2half_rn(s * __half2float(og[base]));
        base += 2048;
    }
}

// ---------------- host launch ----------------
extern "C" void kernel_launch(void* const* d_in, const int* in_sizes, int n_in,
                              void* d_out, int out_size) {
    const float* x    = (const float*)d_in[0];
    const float* mem  = (const float*)d_in[1];
    const float* ln1w = (const float*)d_in[2];
    const float* ln1b = (const float*)d_in[3];
    const float* wf   = (const float*)d_in[4];
    const float* wfb  = (const float*)d_in[5];
    const float* wi   = (const float*)d_in[6];
    const float* wig  = (const float*)d_in[7];
    const float* wigb = (const float*)d_in[8];
    const float* wog  = (const float*)d_in[9];
    const float* wogb = (const float*)d_in[10];
    const float* wo   = (const float*)d_in[11];
    const float* ln2w = (const float*)d_in[12];
    const float* ln2b = (const float*)d_in[13];
    const float* fwi  = (const float*)d_in[14];
    const float* fwg  = (const float*)d_in[15];
    const float* fwgb = (const float*)d_in[16];
    const float* fwo  = (const float*)d_in[17];
    const float* fwob = (const float*)d_in[18];
    float* out = (float*)d_out;

    float *x2, *Ac, *Sc, *Hc;
    __half *wH, *yh, *zh, *gh, *zi, *b0h, *b1h, *rbh, *ogh;
    cudaGetSymbolAddress((void**)&x2, g_x2);
    cudaGetSymbolAddress((void**)&Ac, g_Ac);
    cudaGetSymbolAddress((void**)&Sc, g_Sc);
    cudaGetSymbolAddress((void**)&Hc, g_Hc);
    cudaGetSymbolAddress((void**)&wH, g_wH);
    cudaGetSymbolAddress((void**)&yh, g_yh);
    cudaGetSymbolAddress((void**)&zh, g_zh);
    cudaGetSymbolAddress((void**)&gh, g_gh);
    cudaGetSymbolAddress((void**)&zi, g_zi);
    cudaGetSymbolAddress((void**)&b0h, g_b0);
    cudaGetSymbolAddress((void**)&b1h, g_b1);
    cudaGetSymbolAddress((void**)&rbh, g_r);
    cudaGetSymbolAddress((void**)&ogh, g_og);

    cudaFuncSetAttribute(gemm_mma, cudaFuncAttributeMaxDynamicSharedMemorySize, GSMEM);

    __half* wiT  = wH + 0 * WSLOT;
    __half* wigT = wH + 1 * WSLOT;
    __half* wfT  = wH + 2 * WSLOT;
    __half* wogT = wH + 3 * WSLOT;
    __half* woT  = wH + 4 * WSLOT;
    __half* fwiT = wH + 5 * WSLOT;
    __half* fwgT = wH + 6 * WSLOT;
    __half* fwoT = wH + 7 * WSLOT;

    TArgs ta;
    ta.s[0] = wi;  ta.d[0] = wiT;  ta.K[0] = E_DIM; ta.N[0] = M_DIM;
    ta.s[1] = wig; ta.d[1] = wigT; ta.K[1] = E_DIM; ta.N[1] = M_DIM;
    ta.s[2] = wf;  ta.d[2] = wfT;  ta.K[2] = E_DIM; ta.N[2] = M_DIM;
    ta.s[3] = wog; ta.d[3] = wogT; ta.K[3] = E_DIM; ta.N[3] = M_DIM;
    ta.s[4] = wo;  ta.d[4] = woT;  ta.K[4] = M_DIM; ta.N[4] = E_DIM;
    ta.s[5] = fwi; ta.d[5] = fwiT; ta.K[5] = E_DIM; ta.N[5] = M_DIM;
    ta.s[6] = fwg; ta.d[6] = fwgT; ta.K[6] = E_DIM; ta.N[6] = M_DIM;
    ta.s[7] = fwo; ta.d[7] = fwoT; ta.K[7] = M_DIM; ta.N[7] = E_DIM;
    dim3 tg(WSLOT / (32 * 32), 8);
    tcvt8<<<tg, dim3(32, 8)>>>(ta);

    ln1024<<<R_ROWS, 256>>>(x, ln1w, ln1b, yh);

    // 4 gate GEMMs in one launch (fp16 outputs)
    {
        GArgs ga;
        ga.g[0] = { wiT,  nullptr, nullptr, b0h, 0 };
        ga.g[1] = { wigT, wigb,    nullptr, b1h, 1 };
        ga.g[2] = { wfT,  wfb,     nullptr, rbh, 1 };
        ga.g[3] = { wogT, wogb,    nullptr, ogh, 1 };
        dim3 gr(M_DIM / 256, R_ROWS / 128, 4);
        gemm_mma<<<gr, 512, GSMEM>>>(yh, ga, E_DIM, M_DIM);
    }

    scan_pass1<<<NCHUNK * 8192 / 256, 256>>>(b0h, b1h, rbh, Ac, Sc);
    scan_pass2<<<8192 / 256, 256>>>(mem, Ac, Sc, Hc, out + (size_t)R_ROWS * E_DIM);
    scan_pass3<<<NCHUNK * 8192 / 256, 256>>>(b0h, b1h, rbh, ogh, Hc, gh);

    // x2 = x + g @ wo
    {
        GArgs ga;
        ga.g[0] = { woT, nullptr, x, x2, 3 };
        dim3 gr(E_DIM / 256, R_ROWS / 128, 1);
        gemm_mma<<<gr, 512, GSMEM>>>(gh, ga, M_DIM, E_DIM);
    }

    ln1024<<<R_ROWS, 256>>>(x2, ln2w, ln2b, zh);

    // FFN in+gate in one launch (fp16 outputs)
    {
        GArgs ga;
        ga.g[0] = { fwiT, nullptr, nullptr, b0h, 0 };
        ga.g[1] = { fwgT, fwgb,    nullptr, b1h, 1 };
        dim3 gr(M_DIM / 256, R_ROWS / 128, 2);
        gemm_mma<<<gr, 512, GSMEM>>>(zh, ga, E_DIM, M_DIM);
    }

    // zi = fp16(b0*b1)
    gateprod<<<R_ROWS * M_DIM / 4 / 256, 256>>>((const __half2*)b0h, (const __half2*)b1h, (__half2*)zi);

    // out = x2 + zi @ fwo + fwob
    {
        GArgs ga;
        ga.g[0] = { fwoT, fwob, x2, out, 3 };
        dim3 gr(E_DIM / 256, R_ROWS / 128, 1);
        gemm_mma<<<gr, 512, GSMEM>>>(zi, ga, M_DIM, E_DIM);
    }
}